// round 12
// baseline (speedup 1.0000x reference)
#include <cuda_runtime.h>
#include <cuda_fp16.h>
#include <math.h>
#include <stdint.h>

#define LL 2
#define HH 16
#define DD 1024
#define HD 64
#define FFD 4096
#define VV 32000
#define SS 1024
#define BB 4
#define BS (BB*SS)   /* 4096 */

// ================= scratch (device globals) =================================
__device__ float g_h  [(size_t)BS*DD];

__device__ __half g_hh [(size_t)BS*DD];
__device__ __half g_qkvh[(size_t)BS*3*DD];
__device__ __half g_oh [(size_t)BS*DD];
__device__ __half g_ffh[(size_t)BS*FFD];
__device__ __half g_th [(size_t)BS*DD];

__device__ __half g_wqkvn[(size_t)LL*DD*3*DD];   // [L][D][3*D]  (K x N)
__device__ __half g_wo_n [(size_t)LL*DD*DD];     // [L][D][D]
__device__ __half g_w1_n [(size_t)LL*DD*FFD];    // [L][D][FF]
__device__ __half g_w2_n [(size_t)LL*FFD*DD];    // [L][FF][D]
__device__ __half g_woutn[(size_t)DD*VV];        // [D][V]
__device__ float g_bqkv[(size_t)LL*3*DD];

// ================= small helpers ============================================
__device__ __forceinline__ uint32_t smem_to_u32(const void* smem_ptr) {
    uint32_t addr;
    asm("{ .reg .u64 tmp; cvta.to.shared.u64 tmp, %1; cvt.u32.u64 %0, tmp; }"
        : "=r"(addr) : "l"(smem_ptr));
    return addr;
}
__device__ __forceinline__ void cp16(uint32_t d, const void* s){
    asm volatile("cp.async.cg.shared.global [%0], [%1], 16;" :: "r"(d), "l"(s) : "memory");
}
__device__ __forceinline__ void ldm_x4(uint32_t* r, uint32_t addr){
    asm volatile("ldmatrix.sync.aligned.m8n8.x4.shared.b16 {%0,%1,%2,%3}, [%4];"
        : "=r"(r[0]), "=r"(r[1]), "=r"(r[2]), "=r"(r[3]) : "r"(addr));
}
__device__ __forceinline__ void ldm_x4_t(uint32_t* r, uint32_t addr){
    asm volatile("ldmatrix.sync.aligned.m8n8.x4.trans.shared.b16 {%0,%1,%2,%3}, [%4];"
        : "=r"(r[0]), "=r"(r[1]), "=r"(r[2]), "=r"(r[3]) : "r"(addr));
}
__device__ __forceinline__ void mma16816(float* c, const uint32_t* a, uint32_t b0, uint32_t b1){
    asm volatile("mma.sync.aligned.m16n8k16.row.col.f32.f16.f16.f32 "
        "{%0,%1,%2,%3}, {%4,%5,%6,%7}, {%8,%9}, {%0,%1,%2,%3};"
        : "+f"(c[0]), "+f"(c[1]), "+f"(c[2]), "+f"(c[3])
        : "r"(a[0]), "r"(a[1]), "r"(a[2]), "r"(a[3]), "r"(b0), "r"(b1));
}
__device__ __forceinline__ float warpSum(float v){
    #pragma unroll
    for (int o = 16; o > 0; o >>= 1) v += __shfl_xor_sync(0xffffffffu, v, o);
    return v;
}
__device__ __forceinline__ float blockSum256(float v, float* sh){
    int lane = threadIdx.x & 31, wid = threadIdx.x >> 5;
    v = warpSum(v);
    if (lane == 0) sh[wid] = v;
    __syncthreads();
    float r = (threadIdx.x < 8) ? sh[threadIdx.x] : 0.f;
    if (threadIdx.x < 32) { r = warpSum(r); if (threadIdx.x == 0) sh[0] = r; }
    __syncthreads();
    float res = sh[0];
    __syncthreads();
    return res;
}
__device__ __forceinline__ float gelu_f(float x){
    return 0.5f * x * (1.0f + erff(x * 0.70710678118654752f));
}
__device__ __forceinline__ void store_half4(__half* p, size_t idx, float4 v){
    *(__half2*)(p+idx)   = __halves2half2(__float2half_rn(v.x), __float2half_rn(v.y));
    *(__half2*)(p+idx+2) = __halves2half2(__float2half_rn(v.z), __float2half_rn(v.w));
}
__device__ __forceinline__ void store_half2(__half* p, size_t idx, float a, float b){
    *(__half2*)(p+idx) = __halves2half2(__float2half_rn(a), __float2half_rn(b));
}
__device__ __forceinline__ uint32_t pack_h2(float a, float b){
    __half2 h = __halves2half2(__float2half_rn(a), __float2half_rn(b));
    return *(uint32_t*)&h;
}
__device__ __forceinline__ uint4 pack_h8(float4 a, float4 b){
    uint4 u;
    u.x = pack_h2(a.x, a.y); u.y = pack_h2(a.z, a.w);
    u.z = pack_h2(b.x, b.y); u.w = pack_h2(b.z, b.w);
    return u;
}

// ================= prep kernels =============================================
__global__ __launch_bounds__(256) void packbias_k(const float* __restrict__ bq,
                                                  const float* __restrict__ bk,
                                                  const float* __restrict__ bv){
    int i = blockIdx.x*256 + threadIdx.x;            // 0..6143
    int l = i / (3*DD), n = i % (3*DD);
    float v = (n < DD) ? bq[l*DD + n] : (n < 2*DD) ? bk[l*DD + n - DD] : bv[l*DD + n - 2*DD];
    g_bqkv[i] = v;
}

// fp32 -> fp16 cast, 8 elems/thread, 16B vector store
__global__ __launch_bounds__(256) void cast_k(const float* __restrict__ in,
                                              __half* __restrict__ out){
    size_t i = ((size_t)blockIdx.x*256 + threadIdx.x)*8;
    float4 a = *(const float4*)(in + i);
    float4 b = *(const float4*)(in + i + 4);
    *(uint4*)(out + i) = pack_h8(a, b);
}

// QKV weight permute+cast: out[l][d][sec*1024 + h*64 + e] = W[l][h][d][e]
// 8 elems along e per thread, 16B store.
__global__ __launch_bounds__(256) void qkvpack_k(const float* __restrict__ W,
                                                 __half* __restrict__ out, int sec){
    size_t i = (size_t)blockIdx.x*256 + threadIdx.x;  // 262144 total
    int e8 = (int)(i & 7);
    int d  = (int)((i >> 3) & 1023);
    int h  = (int)((i >> 13) & 15);
    int l  = (int)(i >> 17);
    const float* src = W + (((size_t)(l*16 + h)*1024 + d)*64 + e8*8);
    float4 a = *(const float4*)(src);
    float4 b = *(const float4*)(src + 4);
    size_t o = ((size_t)(l*1024 + d)*3072) + sec*1024 + h*64 + e8*8;
    *(uint4*)(out + o) = pack_h8(a, b);
}

__global__ __launch_bounds__(256) void embed_k(const int* __restrict__ x,
                                               const float* __restrict__ tok,
                                               const float* __restrict__ pos){
    int t = blockIdx.x;
    int s = t & (SS - 1);
    int id = x[t];
    int j = threadIdx.x * 4;
    float4 a = *(const float4*)(tok + (size_t)id * DD + j);
    float4 p = *(const float4*)(pos + (size_t)s  * DD + j);
    float4 r; r.x = a.x + p.x; r.y = a.y + p.y; r.z = a.z + p.z; r.w = a.w + p.w;
    size_t idx = (size_t)t * DD + j;
    *(float4*)(g_h + idx) = r;
    store_half4(g_hh, idx, r);
}

// ================= fp16 NN GEMM via mma.sync ================================
// C[M,N] = A[M][K] * B[K][N] (+bias).  B fed via ldmatrix.trans.
// block tile 128x128, Kc=32, 4 warps (warp tile 64x64), cp.async double buffer.
// op0: f32 out + bias.  op1: gelu(out+bias) -> fp16.  op2: bias -> fp16.
#define PADK 40            /* A row stride, fp16 elems */
#define PADN 136           /* B row stride, fp16 elems (272 B, conflict-free) */
#define ASZ (128*PADK*2)   /* 10240 */
#define BSZ (32*PADN*2)    /* 8704  */
#define GBUF (ASZ+BSZ)     /* 18944 */
#define GM_SMEM (2*GBUF)   /* 37888 */
__global__ __launch_bounds__(128, 2) void gemm_nn(
    const __half* __restrict__ A, const __half* __restrict__ B,
    const float* __restrict__ bias,
    float* __restrict__ Cf, __half* __restrict__ Ch,
    int K_, int ldb, int ldc, int op)
{
    extern __shared__ char smem[];
    uint32_t sb = smem_to_u32(smem);
    int tid = threadIdx.x, lane = tid & 31, wid = tid >> 5;
    int wm = wid & 1, wn = wid >> 1;            // 2x2 warp grid, 64x64 tiles
    long row0 = (long)blockIdx.x * 128;
    long col0 = (long)blockIdx.y * 128;

    float acc[4][8][4];
    #pragma unroll
    for (int i = 0; i < 4; i++)
        #pragma unroll
        for (int j = 0; j < 8; j++)
            #pragma unroll
            for (int q = 0; q < 4; q++) acc[i][j][q] = 0.f;

    auto load_chunk = [&](int c, int buf){
        long k0 = (long)c * 32;
        uint32_t base = sb + (uint32_t)buf * GBUF;
        #pragma unroll
        for (int i = tid; i < 512; i += 128){       // A: 128 rows x 4 units
            int r = i >> 2, seg = (i & 3) * 8;
            cp16(base + (uint32_t)(r*PADK + seg)*2, A + (row0 + r)*(long)K_ + k0 + seg);
        }
        #pragma unroll
        for (int i = tid; i < 512; i += 128){       // B: 32 k-rows x 16 units
            int r = i >> 4, u = (i & 15) * 8;
            cp16(base + ASZ + (uint32_t)(r*PADN + u)*2, B + (k0 + r)*(long)ldb + col0 + u);
        }
        asm volatile("cp.async.commit_group;" ::: "memory");
    };

    const int NC = K_ >> 5;
    load_chunk(0, 0);

    int m_local = (lane & 7) | (lane & 8);
    int k_off = (lane >> 4) * 8;
    int t_row = lane & 15, t_col = (lane >> 4) * 8;

    for (int c = 0; c < NC; ++c){
        int buf = c & 1;
        asm volatile("cp.async.wait_group 0;" ::: "memory");
        __syncthreads();
        if (c + 1 < NC) load_chunk(c + 1, buf ^ 1);

        uint32_t base = sb + (uint32_t)buf * GBUF;
        #pragma unroll
        for (int ks = 0; ks < 2; ++ks){
            uint32_t a_h[4][4];
            #pragma unroll
            for (int am = 0; am < 4; ++am){
                uint32_t roff = (uint32_t)((wm*64 + am*16 + m_local) * PADK + ks*16 + k_off) * 2;
                ldm_x4(a_h[am], base + roff);
            }
            uint32_t bt[4][4];
            #pragma unroll
            for (int g2 = 0; g2 < 4; ++g2){
                uint32_t voff = (uint32_t)((ks*16 + t_row)*PADN + wn*64 + g2*16 + t_col) * 2;
                ldm_x4_t(bt[g2], base + ASZ + voff);
            }
            #pragma unroll
            for (int mt = 0; mt < 4; ++mt)
                #pragma unroll
                for (int nt = 0; nt < 8; ++nt){
                    int g2 = nt >> 1, sub = (nt & 1) * 2;
                    mma16816(acc[mt][nt], a_h[mt], bt[g2][sub], bt[g2][sub+1]);
                }
        }
    }

    // epilogue
    #pragma unroll
    for (int mt = 0; mt < 4; ++mt){
        #pragma unroll
        for (int nt = 0; nt < 8; ++nt){
            long row = row0 + wm*64 + mt*16 + (lane >> 2);
            long col = col0 + wn*64 + nt*8 + (lane & 3)*2;
            float b0 = bias[col], b1 = bias[col+1];
            float v0 = acc[mt][nt][0] + b0, v1 = acc[mt][nt][1] + b1;
            float v2 = acc[mt][nt][2] + b0, v3 = acc[mt][nt][3] + b1;
            if (op == 0){
                *(float2*)(Cf + row*(long)ldc + col)     = make_float2(v0, v1);
                *(float2*)(Cf + (row+8)*(long)ldc + col) = make_float2(v2, v3);
            } else if (op == 1){
                store_half2(Ch, (size_t)(row*(long)ldc + col),     gelu_f(v0), gelu_f(v1));
                store_half2(Ch, (size_t)((row+8)*(long)ldc + col), gelu_f(v2), gelu_f(v3));
            } else {
                store_half2(Ch, (size_t)(row*(long)ldc + col),     v0, v1);
                store_half2(Ch, (size_t)((row+8)*(long)ldc + col), v2, v3);
            }
        }
    }
}

// ================= fused flash attention ====================================
#define PADQ 72
#define FL_Q   (128*PADQ*2)              /* 18432 */
#define FL_KV  (128*PADQ*2)
#define FL_BUF (2*FL_KV)                 /* 36864 */
#define FL_SMEM (FL_Q + 2*FL_BUF)        /* 92160 */
__global__ __launch_bounds__(256, 1) void flash_k(
    const __half* __restrict__ qkvh, __half* __restrict__ oh)
{
    extern __shared__ char smem[];
    uint32_t sb = smem_to_u32(smem);
    int z = blockIdx.x; int b = z & 3, hd = z >> 2;
    int rb = blockIdx.y;
    long qbase = (long)b*SS*(3*DD) + hd*HD;
    long kbase = qbase + DD;
    long vbase = qbase + 2*DD;
    long obase = (long)b*SS*DD + hd*HD;
    int tid = threadIdx.x, lane = tid & 31, wid = tid >> 5;
    long row0 = (long)rb * 128;

    #pragma unroll
    for (int i = tid; i < 1024; i += 256){
        int r = i >> 3, u = (i & 7) * 8;
        cp16(sb + (uint32_t)(r*PADQ + u)*2, qkvh + qbase + (row0 + r)*(long)(3*DD) + u);
    }
    asm volatile("cp.async.commit_group;" ::: "memory");

    auto load_kv = [&](int c, int buf){
        uint32_t base = sb + FL_Q + (uint32_t)buf * FL_BUF;
        long k0 = (long)c * 128;
        #pragma unroll
        for (int i = tid; i < 1024; i += 256){
            int r = i >> 3, u = (i & 7) * 8;
            uint32_t soff = (uint32_t)(r*PADQ + u)*2;
            cp16(base + soff,         qkvh + kbase + (k0 + r)*(long)(3*DD) + u);
            cp16(base + FL_KV + soff, qkvh + vbase + (k0 + r)*(long)(3*DD) + u);
        }
        asm volatile("cp.async.commit_group;" ::: "memory");
    };
    const int nchunks = rb + 1;
    load_kv(0, 0);
    asm volatile("cp.async.wait_group 0;" ::: "memory");
    __syncthreads();

    int m_local = (lane & 7) | (lane & 8);
    int k_off = (lane >> 4) * 8;
    int t_row = lane & 15, t_col = (lane >> 4) * 8;
    int rA = lane >> 2;
    int colb = (lane & 3) * 2;

    uint32_t qf[4][4];
    #pragma unroll
    for (int ks = 0; ks < 4; ++ks){
        uint32_t roff = (uint32_t)((wid*16 + m_local)*PADQ + ks*16 + k_off)*2;
        ldm_x4(qf[ks], sb + roff);
    }

    float oacc[8][4];
    #pragma unroll
    for (int j = 0; j < 8; j++)
        #pragma unroll
        for (int q = 0; q < 4; q++) oacc[j][q] = 0.f;
    float m0 = -1e30f, m1 = -1e30f, l0 = 0.f, l1 = 0.f;

    for (int c = 0; c < nchunks; ++c){
        int buf = c & 1;
        if (c > 0){
            asm volatile("cp.async.wait_group 0;" ::: "memory");
            __syncthreads();
        }
        if (c + 1 < nchunks) load_kv(c + 1, buf ^ 1);
        uint32_t kb = sb + FL_Q + (uint32_t)buf * FL_BUF;

        float s[16][4];
        #pragma unroll
        for (int j = 0; j < 16; j++)
            #pragma unroll
            for (int q = 0; q < 4; q++) s[j][q] = 0.f;
        #pragma unroll
        for (int ks = 0; ks < 4; ++ks){
            uint32_t bh[8][4];
            #pragma unroll
            for (int nt2 = 0; nt2 < 8; ++nt2){
                uint32_t roff = (uint32_t)((nt2*16 + m_local)*PADQ + ks*16 + k_off)*2;
                ldm_x4(bh[nt2], kb + roff);
            }
            #pragma unroll
            for (int nt = 0; nt < 16; ++nt){
                int q = nt >> 1, rs = nt & 1;
                mma16816(s[nt], qf[ks], bh[q][rs], bh[q][rs+2]);
            }
        }

        bool diag = (c == rb);
        float cm0 = -1e30f, cm1 = -1e30f;
        #pragma unroll
        for (int nt = 0; nt < 16; ++nt){
            int cl = nt*8 + colb;
            int r_lo = wid*16 + rA, r_hi = r_lo + 8;
            #pragma unroll
            for (int q = 0; q < 4; q++) s[nt][q] *= 0.125f;
            if (diag){
                if (cl     > r_lo) s[nt][0] = -1e30f;
                if (cl + 1 > r_lo) s[nt][1] = -1e30f;
                if (cl     > r_hi) s[nt][2] = -1e30f;
                if (cl + 1 > r_hi) s[nt][3] = -1e30f;
            }
            cm0 = fmaxf(cm0, fmaxf(s[nt][0], s[nt][1]));
            cm1 = fmaxf(cm1, fmaxf(s[nt][2], s[nt][3]));
        }
        cm0 = fmaxf(cm0, __shfl_xor_sync(0xffffffffu, cm0, 1));
        cm0 = fmaxf(cm0, __shfl_xor_sync(0xffffffffu, cm0, 2));
        cm1 = fmaxf(cm1, __shfl_xor_sync(0xffffffffu, cm1, 1));
        cm1 = fmaxf(cm1, __shfl_xor_sync(0xffffffffu, cm1, 2));
        float mn0 = fmaxf(m0, cm0), mn1 = fmaxf(m1, cm1);
        float al0 = expf(m0 - mn0), al1 = expf(m1 - mn1);
        m0 = mn0; m1 = mn1;

        float ls0 = 0.f, ls1 = 0.f;
        #pragma unroll
        for (int nt = 0; nt < 16; ++nt){
            s[nt][0] = expf(s[nt][0] - mn0);
            s[nt][1] = expf(s[nt][1] - mn0);
            s[nt][2] = expf(s[nt][2] - mn1);
            s[nt][3] = expf(s[nt][3] - mn1);
            ls0 += s[nt][0] + s[nt][1];
            ls1 += s[nt][2] + s[nt][3];
        }
        ls0 += __shfl_xor_sync(0xffffffffu, ls0, 1);
        ls0 += __shfl_xor_sync(0xffffffffu, ls0, 2);
        ls1 += __shfl_xor_sync(0xffffffffu, ls1, 1);
        ls1 += __shfl_xor_sync(0xffffffffu, ls1, 2);
        l0 = l0 * al0 + ls0;
        l1 = l1 * al1 + ls1;

        #pragma unroll
        for (int nt = 0; nt < 8; ++nt){
            oacc[nt][0] *= al0; oacc[nt][1] *= al0;
            oacc[nt][2] *= al1; oacc[nt][3] *= al1;
        }

        uint32_t vb = kb + FL_KV;
        #pragma unroll
        for (int kk = 0; kk < 8; ++kk){
            uint32_t a[4];
            a[0] = pack_h2(s[2*kk][0],   s[2*kk][1]);
            a[1] = pack_h2(s[2*kk][2],   s[2*kk][3]);
            a[2] = pack_h2(s[2*kk+1][0], s[2*kk+1][1]);
            a[3] = pack_h2(s[2*kk+1][2], s[2*kk+1][3]);
            uint32_t bv[4][4];
            #pragma unroll
            for (int g2 = 0; g2 < 4; ++g2){
                uint32_t voff = (uint32_t)((kk*16 + t_row)*PADQ + g2*16 + t_col)*2;
                ldm_x4_t(bv[g2], vb + voff);
            }
            #pragma unroll
            for (int nt = 0; nt < 8; ++nt){
                int g2 = nt >> 1, sub = (nt & 1) * 2;
                mma16816(oacc[nt], a, bv[g2][sub], bv[g2][sub+1]);
            }
        }
    }

    float inv0 = 1.f / l0, inv1 = 1.f / l1;
    #pragma unroll
    for (int nt = 0; nt < 8; ++nt){
        long row = row0 + wid*16 + rA;
        long col = nt*8 + colb;
        size_t idx = (size_t)(obase + row*(long)DD + col);
        store_half2(oh, idx,        oacc[nt][0]*inv0, oacc[nt][1]*inv0);
        store_half2(oh, idx + 8*DD, oacc[nt][2]*inv1, oacc[nt][3]*inv1);
    }
}

// ================= pointwise ================================================
__global__ __launch_bounds__(256) void add_ln_k(float* __restrict__ h,
                                                const __half* __restrict__ delta,
                                                const float* __restrict__ w,
                                                const float* __restrict__ b,
                                                float* __restrict__ out2){
    long t = blockIdx.x;
    int tid = threadIdx.x;
    int j = tid * 4;
    __shared__ float sh[8];
    float4 hv = *(const float4*)(h + t * DD + j);
    __half2 d0 = *(const __half2*)(delta + t * DD + j);
    __half2 d1 = *(const __half2*)(delta + t * DD + j + 2);
    float x[4] = {hv.x + __low2float(d0), hv.y + __high2float(d0),
                  hv.z + __low2float(d1), hv.w + __high2float(d1)};
    float s = x[0] + x[1] + x[2] + x[3];
    float mean = blockSum256(s, sh) * (1.f / DD);
    float sq = 0.f;
    #pragma unroll
    for (int c = 0; c < 4; c++){ float d = x[c] - mean; sq += d * d; }
    float var = blockSum256(sq, sh) * (1.f / DD);
    float inv = rsqrtf(var + 1e-5f);
    float4 o;
    o.x = (x[0]-mean)*inv*w[j+0] + b[j+0];
    o.y = (x[1]-mean)*inv*w[j+1] + b[j+1];
    o.z = (x[2]-mean)*inv*w[j+2] + b[j+2];
    o.w = (x[3]-mean)*inv*w[j+3] + b[j+3];
    size_t idx = (size_t)t * DD + j;
    *(float4*)(h + idx) = o;
    store_half4(g_hh, idx, o);
    if (out2) *(float4*)(out2 + idx) = o;
}

// ================= launch ===================================================
extern "C" void kernel_launch(void* const* d_in, const int* in_sizes, int n_in,
                              void* d_out, int out_size)
{
    const int*   x    = (const int*)  d_in[0];
    const float* tok  = (const float*)d_in[1];
    const float* pos  = (const float*)d_in[2];
    const float* Wq   = (const float*)d_in[3];
    const float* bq   = (const float*)d_in[4];
    const float* Wk   = (const float*)d_in[5];
    const float* bk   = (const float*)d_in[6];
    const float* Wv   = (const float*)d_in[7];
    const float* bv   = (const float*)d_in[8];
    const float* Wo   = (const float*)d_in[9];
    const float* bo   = (const float*)d_in[10];
    const float* ln1w = (const float*)d_in[11];
    const float* ln1b = (const float*)d_in[12];
    const float* ln2w = (const float*)d_in[13];
    const float* ln2b = (const float*)d_in[14];
    const float* W1   = (const float*)d_in[15];
    const float* b1   = (const float*)d_in[16];
    const float* W2   = (const float*)d_in[17];
    const float* b2   = (const float*)d_in[18];
    const float* Wout = (const float*)d_in[19];
    const float* bout = (const float*)d_in[20];
    float* out = (float*)d_out;

    static int attr_set = 0;
    if (!attr_set){
        cudaFuncSetAttribute(gemm_nn, cudaFuncAttributeMaxDynamicSharedMemorySize, GM_SMEM);
        cudaFuncSetAttribute(flash_k, cudaFuncAttributeMaxDynamicSharedMemorySize, FL_SMEM);
        attr_set = 1;
    }

    float *h, *bqkv;
    __half *hh, *qh, *oh, *ffh, *th;
    __half *wqn, *won, *w1n, *w2n, *woutn;
    cudaGetSymbolAddress((void**)&h,    g_h);
    cudaGetSymbolAddress((void**)&bqkv, g_bqkv);
    cudaGetSymbolAddress((void**)&hh,   g_hh);
    cudaGetSymbolAddress((void**)&qh,   g_qkvh);
    cudaGetSymbolAddress((void**)&oh,   g_oh);
    cudaGetSymbolAddress((void**)&ffh,  g_ffh);
    cudaGetSymbolAddress((void**)&th,   g_th);
    cudaGetSymbolAddress((void**)&wqn,  g_wqkvn);
    cudaGetSymbolAddress((void**)&won,  g_wo_n);
    cudaGetSymbolAddress((void**)&w1n,  g_w1_n);
    cudaGetSymbolAddress((void**)&w2n,  g_w2_n);
    cudaGetSymbolAddress((void**)&woutn,g_woutn);

    // --- weight prep: permute/cast only (vectorized) ---
    packbias_k<<<24, 256>>>(bq, bk, bv);
    qkvpack_k<<<1024, 256>>>(Wq, wqn, 0);
    qkvpack_k<<<1024, 256>>>(Wk, wqn, 1);
    qkvpack_k<<<1024, 256>>>(Wv, wqn, 2);
    cast_k<<<1024,  256>>>(Wo,   won);    // 2*1024*1024 / 2048
    cast_k<<<4096,  256>>>(W1,   w1n);    // 2*1024*4096 / 2048
    cast_k<<<4096,  256>>>(W2,   w2n);
    cast_k<<<16000, 256>>>(Wout, woutn);  // 1024*32000 / 2048

    embed_k<<<BS, 256>>>(x, tok, pos);

    for (int l = 0; l < LL; l++){
        // QKV: [4096,1024] x [1024,3072] -> fp16
        gemm_nn<<<dim3(BS/128, 3*DD/128), 128, GM_SMEM>>>(
            hh, wqn + (long)l*DD*3*DD, bqkv + (long)l*3*DD,
            0, qh, DD, 3*DD, 3*DD, 2);
        // fused attention
        flash_k<<<dim3(HH*BB, SS/128), 256, FL_SMEM>>>(qh, oh);
        // Wo -> fp16 delta
        gemm_nn<<<dim3(BS/128, DD/128), 128, GM_SMEM>>>(
            oh, won + (long)l*DD*DD, bo + (long)l*DD,
            0, th, DD, DD, DD, 2);
        add_ln_k<<<BS, 256>>>(h, th, ln1w + (long)l*DD, ln1b + (long)l*DD, 0);
        // W1 + GELU -> ff (fp16)
        gemm_nn<<<dim3(BS/128, FFD/128), 128, GM_SMEM>>>(
            hh, w1n + (long)l*DD*FFD, b1 + (long)l*FFD,
            0, ffh, DD, FFD, FFD, 1);
        // W2 -> fp16 delta
        gemm_nn<<<dim3(BS/128, DD/128), 128, GM_SMEM>>>(
            ffh, w2n + (long)l*FFD*DD, b2 + (long)l*DD,
            0, th, FFD, DD, DD, 2);
        add_ln_k<<<BS, 256>>>(h, th, ln2w + (long)l*DD, ln2b + (long)l*DD,
                              (l == LL-1) ? (out + (long)BS*VV) : 0);
    }

    // logits (fp32 out)
    gemm_nn<<<dim3(BS/128, VV/128), 128, GM_SMEM>>>(
        hh, woutn, bout, out, 0, DD, VV, VV, 0);
}

// round 13
// speedup vs baseline: 1.0047x; 1.0047x over previous
#include <cuda_runtime.h>
#include <cuda_fp16.h>
#include <math.h>
#include <stdint.h>

#define LL 2
#define HH 16
#define DD 1024
#define HD 64
#define FFD 4096
#define VV 32000
#define SS 1024
#define BB 4
#define BS (BB*SS)   /* 4096 */

// ================= scratch (device globals) =================================
__device__ float g_h  [(size_t)BS*DD];

__device__ __half g_hh [(size_t)BS*DD];
__device__ __half g_qkvh[(size_t)BS*3*DD];
__device__ __half g_oh [(size_t)BS*DD];
__device__ __half g_ffh[(size_t)BS*FFD];
__device__ __half g_th [(size_t)BS*DD];

__device__ __half g_wqkvn[(size_t)LL*DD*3*DD];   // [L][D][3*D]  (K x N)
__device__ __half g_wo_n [(size_t)LL*DD*DD];     // [L][D][D]
__device__ __half g_w1_n [(size_t)LL*DD*FFD];    // [L][D][FF]
__device__ __half g_w2_n [(size_t)LL*FFD*DD];    // [L][FF][D]
__device__ __half g_woutn[(size_t)DD*VV];        // [D][V]
__device__ float g_bqkv[(size_t)LL*3*DD];

// ================= small helpers ============================================
__device__ __forceinline__ uint32_t smem_to_u32(const void* smem_ptr) {
    uint32_t addr;
    asm("{ .reg .u64 tmp; cvta.to.shared.u64 tmp, %1; cvt.u32.u64 %0, tmp; }"
        : "=r"(addr) : "l"(smem_ptr));
    return addr;
}
__device__ __forceinline__ void cp16(uint32_t d, const void* s){
    asm volatile("cp.async.cg.shared.global [%0], [%1], 16;" :: "r"(d), "l"(s) : "memory");
}
__device__ __forceinline__ void ldm_x4(uint32_t* r, uint32_t addr){
    asm volatile("ldmatrix.sync.aligned.m8n8.x4.shared.b16 {%0,%1,%2,%3}, [%4];"
        : "=r"(r[0]), "=r"(r[1]), "=r"(r[2]), "=r"(r[3]) : "r"(addr));
}
__device__ __forceinline__ void ldm_x4_t(uint32_t* r, uint32_t addr){
    asm volatile("ldmatrix.sync.aligned.m8n8.x4.trans.shared.b16 {%0,%1,%2,%3}, [%4];"
        : "=r"(r[0]), "=r"(r[1]), "=r"(r[2]), "=r"(r[3]) : "r"(addr));
}
__device__ __forceinline__ void mma16816(float* c, const uint32_t* a, uint32_t b0, uint32_t b1){
    asm volatile("mma.sync.aligned.m16n8k16.row.col.f32.f16.f16.f32 "
        "{%0,%1,%2,%3}, {%4,%5,%6,%7}, {%8,%9}, {%0,%1,%2,%3};"
        : "+f"(c[0]), "+f"(c[1]), "+f"(c[2]), "+f"(c[3])
        : "r"(a[0]), "r"(a[1]), "r"(a[2]), "r"(a[3]), "r"(b0), "r"(b1));
}
__device__ __forceinline__ float warpSum(float v){
    #pragma unroll
    for (int o = 16; o > 0; o >>= 1) v += __shfl_xor_sync(0xffffffffu, v, o);
    return v;
}
__device__ __forceinline__ float blockSum256(float v, float* sh){
    int lane = threadIdx.x & 31, wid = threadIdx.x >> 5;
    v = warpSum(v);
    if (lane == 0) sh[wid] = v;
    __syncthreads();
    float r = (threadIdx.x < 8) ? sh[threadIdx.x] : 0.f;
    if (threadIdx.x < 32) { r = warpSum(r); if (threadIdx.x == 0) sh[0] = r; }
    __syncthreads();
    float res = sh[0];
    __syncthreads();
    return res;
}
__device__ __forceinline__ float gelu_f(float x){
    return 0.5f * x * (1.0f + erff(x * 0.70710678118654752f));
}
__device__ __forceinline__ void store_half4(__half* p, size_t idx, float4 v){
    *(__half2*)(p+idx)   = __halves2half2(__float2half_rn(v.x), __float2half_rn(v.y));
    *(__half2*)(p+idx+2) = __halves2half2(__float2half_rn(v.z), __float2half_rn(v.w));
}
__device__ __forceinline__ void store_half2(__half* p, size_t idx, float a, float b){
    *(__half2*)(p+idx) = __halves2half2(__float2half_rn(a), __float2half_rn(b));
}
__device__ __forceinline__ uint32_t pack_h2(float a, float b){
    __half2 h = __halves2half2(__float2half_rn(a), __float2half_rn(b));
    return *(uint32_t*)&h;
}
__device__ __forceinline__ uint4 pack_h8(float4 a, float4 b){
    uint4 u;
    u.x = pack_h2(a.x, a.y); u.y = pack_h2(a.z, a.w);
    u.z = pack_h2(b.x, b.y); u.w = pack_h2(b.z, b.w);
    return u;
}

// ================= prep kernels =============================================
__global__ __launch_bounds__(256) void packbias_k(const float* __restrict__ bq,
                                                  const float* __restrict__ bk,
                                                  const float* __restrict__ bv){
    int i = blockIdx.x*256 + threadIdx.x;            // 0..6143
    int l = i / (3*DD), n = i % (3*DD);
    float v = (n < DD) ? bq[l*DD + n] : (n < 2*DD) ? bk[l*DD + n - DD] : bv[l*DD + n - 2*DD];
    g_bqkv[i] = v;
}

// fp32 -> fp16 cast, 8 elems/thread, 16B vector store
__global__ __launch_bounds__(256) void cast_k(const float* __restrict__ in,
                                              __half* __restrict__ out){
    size_t i = ((size_t)blockIdx.x*256 + threadIdx.x)*8;
    float4 a = *(const float4*)(in + i);
    float4 b = *(const float4*)(in + i + 4);
    *(uint4*)(out + i) = pack_h8(a, b);
}

// QKV weight permute+cast: out[l][d][sec*1024 + h*64 + e] = W[l][h][d][e]
__global__ __launch_bounds__(256) void qkvpack_k(const float* __restrict__ W,
                                                 __half* __restrict__ out, int sec){
    size_t i = (size_t)blockIdx.x*256 + threadIdx.x;  // 262144 total
    int e8 = (int)(i & 7);
    int d  = (int)((i >> 3) & 1023);
    int h  = (int)((i >> 13) & 15);
    int l  = (int)(i >> 17);
    const float* src = W + (((size_t)(l*16 + h)*1024 + d)*64 + e8*8);
    float4 a = *(const float4*)(src);
    float4 b = *(const float4*)(src + 4);
    size_t o = ((size_t)(l*1024 + d)*3072) + sec*1024 + h*64 + e8*8;
    *(uint4*)(out + o) = pack_h8(a, b);
}

__global__ __launch_bounds__(256) void embed_k(const int* __restrict__ x,
                                               const float* __restrict__ tok,
                                               const float* __restrict__ pos){
    int t = blockIdx.x;
    int s = t & (SS - 1);
    int id = x[t];
    int j = threadIdx.x * 4;
    float4 a = *(const float4*)(tok + (size_t)id * DD + j);
    float4 p = *(const float4*)(pos + (size_t)s  * DD + j);
    float4 r; r.x = a.x + p.x; r.y = a.y + p.y; r.z = a.z + p.z; r.w = a.w + p.w;
    size_t idx = (size_t)t * DD + j;
    *(float4*)(g_h + idx) = r;
    store_half4(g_hh, idx, r);
}

// ================= fp16 NN GEMM via mma.sync ================================
// C[M,N] = A[M][K] * B[K][N] (+bias).  B fed via ldmatrix.trans.
// block tile 128x128, Kc=32, 8 warps (warp tile 32x64), cp.async 3-stage.
// op0: f32 out + bias.  op1: gelu(out+bias) -> fp16.  op2: bias -> fp16.
#define PADK 40            /* A row stride, fp16 elems */
#define PADN 136           /* B row stride, fp16 elems (272 B, conflict-free) */
#define ASZ (128*PADK*2)   /* 10240 */
#define BSZ (32*PADN*2)    /* 8704  */
#define GBUF (ASZ+BSZ)     /* 18944 */
#define GM_SMEM (3*GBUF)   /* 56832, 3-stage */
__global__ __launch_bounds__(256, 2) void gemm_nn(
    const __half* __restrict__ A, const __half* __restrict__ B,
    const float* __restrict__ bias,
    float* __restrict__ Cf, __half* __restrict__ Ch,
    int K_, int ldb, int ldc, int op)
{
    extern __shared__ char smem[];
    uint32_t sb = smem_to_u32(smem);
    int tid = threadIdx.x, lane = tid & 31, wid = tid >> 5;
    int wm = wid & 3, wn = wid >> 2;            // 4x2 warp grid, 32x64 tiles
    long row0 = (long)blockIdx.x * 128;
    long col0 = (long)blockIdx.y * 128;

    float acc[2][8][4];
    #pragma unroll
    for (int i = 0; i < 2; i++)
        #pragma unroll
        for (int j = 0; j < 8; j++)
            #pragma unroll
            for (int q = 0; q < 4; q++) acc[i][j][q] = 0.f;

    auto load_chunk = [&](int c, int buf){
        long k0 = (long)c * 32;
        uint32_t base = sb + (uint32_t)buf * GBUF;
        #pragma unroll
        for (int i = tid; i < 512; i += 256){       // A: 128 rows x 4 units
            int r = i >> 2, seg = (i & 3) * 8;
            cp16(base + (uint32_t)(r*PADK + seg)*2, A + (row0 + r)*(long)K_ + k0 + seg);
        }
        #pragma unroll
        for (int i = tid; i < 512; i += 256){       // B: 32 k-rows x 16 units
            int r = i >> 4, u = (i & 15) * 8;
            cp16(base + ASZ + (uint32_t)(r*PADN + u)*2, B + (k0 + r)*(long)ldb + col0 + u);
        }
        asm volatile("cp.async.commit_group;" ::: "memory");
    };

    const int NC = K_ >> 5;
    load_chunk(0, 0);
    if (NC > 1) load_chunk(1, 1);

    int m_local = (lane & 7) | (lane & 8);
    int k_off = (lane >> 4) * 8;
    int t_row = lane & 15, t_col = (lane >> 4) * 8;

    int buf = 0;
    for (int c = 0; c < NC; ++c){
        if (c + 1 < NC){
            asm volatile("cp.async.wait_group 1;" ::: "memory");
        } else {
            asm volatile("cp.async.wait_group 0;" ::: "memory");
        }
        __syncthreads();
        if (c + 2 < NC){
            int nb = buf + 2; if (nb >= 3) nb -= 3;
            load_chunk(c + 2, nb);
        }

        uint32_t base = sb + (uint32_t)buf * GBUF;
        #pragma unroll
        for (int ks = 0; ks < 2; ++ks){
            uint32_t a_h[2][4];
            #pragma unroll
            for (int am = 0; am < 2; ++am){
                uint32_t roff = (uint32_t)((wm*32 + am*16 + m_local) * PADK + ks*16 + k_off) * 2;
                ldm_x4(a_h[am], base + roff);
            }
            uint32_t bt[4][4];
            #pragma unroll
            for (int g2 = 0; g2 < 4; ++g2){
                uint32_t voff = (uint32_t)((ks*16 + t_row)*PADN + wn*64 + g2*16 + t_col) * 2;
                ldm_x4_t(bt[g2], base + ASZ + voff);
            }
            #pragma unroll
            for (int mt = 0; mt < 2; ++mt)
                #pragma unroll
                for (int nt = 0; nt < 8; ++nt){
                    int g2 = nt >> 1, sub = (nt & 1) * 2;
                    mma16816(acc[mt][nt], a_h[mt], bt[g2][sub], bt[g2][sub+1]);
                }
        }
        if (++buf >= 3) buf = 0;
    }

    // epilogue
    #pragma unroll
    for (int mt = 0; mt < 2; ++mt){
        #pragma unroll
        for (int nt = 0; nt < 8; ++nt){
            long row = row0 + wm*32 + mt*16 + (lane >> 2);
            long col = col0 + wn*64 + nt*8 + (lane & 3)*2;
            float b0 = bias[col], b1 = bias[col+1];
            float v0 = acc[mt][nt][0] + b0, v1 = acc[mt][nt][1] + b1;
            float v2 = acc[mt][nt][2] + b0, v3 = acc[mt][nt][3] + b1;
            if (op == 0){
                *(float2*)(Cf + row*(long)ldc + col)     = make_float2(v0, v1);
                *(float2*)(Cf + (row+8)*(long)ldc + col) = make_float2(v2, v3);
            } else if (op == 1){
                store_half2(Ch, (size_t)(row*(long)ldc + col),     gelu_f(v0), gelu_f(v1));
                store_half2(Ch, (size_t)((row+8)*(long)ldc + col), gelu_f(v2), gelu_f(v3));
            } else {
                store_half2(Ch, (size_t)(row*(long)ldc + col),     v0, v1);
                store_half2(Ch, (size_t)((row+8)*(long)ldc + col), v2, v3);
            }
        }
    }
}

// ================= fused flash attention ====================================
#define PADQ 72
#define FL_Q   (128*PADQ*2)              /* 18432 */
#define FL_KV  (128*PADQ*2)
#define FL_BUF (2*FL_KV)                 /* 36864 */
#define FL_SMEM (FL_Q + 2*FL_BUF)        /* 92160 */
__global__ __launch_bounds__(256, 1) void flash_k(
    const __half* __restrict__ qkvh, __half* __restrict__ oh)
{
    extern __shared__ char smem[];
    uint32_t sb = smem_to_u32(smem);
    int z = blockIdx.x; int b = z & 3, hd = z >> 2;
    int rb = blockIdx.y;
    long qbase = (long)b*SS*(3*DD) + hd*HD;
    long kbase = qbase + DD;
    long vbase = qbase + 2*DD;
    long obase = (long)b*SS*DD + hd*HD;
    int tid = threadIdx.x, lane = tid & 31, wid = tid >> 5;
    long row0 = (long)rb * 128;

    #pragma unroll
    for (int i = tid; i < 1024; i += 256){
        int r = i >> 3, u = (i & 7) * 8;
        cp16(sb + (uint32_t)(r*PADQ + u)*2, qkvh + qbase + (row0 + r)*(long)(3*DD) + u);
    }
    asm volatile("cp.async.commit_group;" ::: "memory");

    auto load_kv = [&](int c, int buf){
        uint32_t base = sb + FL_Q + (uint32_t)buf * FL_BUF;
        long k0 = (long)c * 128;
        #pragma unroll
        for (int i = tid; i < 1024; i += 256){
            int r = i >> 3, u = (i & 7) * 8;
            uint32_t soff = (uint32_t)(r*PADQ + u)*2;
            cp16(base + soff,         qkvh + kbase + (k0 + r)*(long)(3*DD) + u);
            cp16(base + FL_KV + soff, qkvh + vbase + (k0 + r)*(long)(3*DD) + u);
        }
        asm volatile("cp.async.commit_group;" ::: "memory");
    };
    const int nchunks = rb + 1;
    load_kv(0, 0);
    asm volatile("cp.async.wait_group 0;" ::: "memory");
    __syncthreads();

    int m_local = (lane & 7) | (lane & 8);
    int k_off = (lane >> 4) * 8;
    int t_row = lane & 15, t_col = (lane >> 4) * 8;
    int rA = lane >> 2;
    int colb = (lane & 3) * 2;

    uint32_t qf[4][4];
    #pragma unroll
    for (int ks = 0; ks < 4; ++ks){
        uint32_t roff = (uint32_t)((wid*16 + m_local)*PADQ + ks*16 + k_off)*2;
        ldm_x4(qf[ks], sb + roff);
    }

    float oacc[8][4];
    #pragma unroll
    for (int j = 0; j < 8; j++)
        #pragma unroll
        for (int q = 0; q < 4; q++) oacc[j][q] = 0.f;
    float m0 = -1e30f, m1 = -1e30f, l0 = 0.f, l1 = 0.f;

    for (int c = 0; c < nchunks; ++c){
        int buf = c & 1;
        if (c > 0){
            asm volatile("cp.async.wait_group 0;" ::: "memory");
            __syncthreads();
        }
        if (c + 1 < nchunks) load_kv(c + 1, buf ^ 1);
        uint32_t kb = sb + FL_Q + (uint32_t)buf * FL_BUF;

        float s[16][4];
        #pragma unroll
        for (int j = 0; j < 16; j++)
            #pragma unroll
            for (int q = 0; q < 4; q++) s[j][q] = 0.f;
        #pragma unroll
        for (int ks = 0; ks < 4; ++ks){
            uint32_t bh[8][4];
            #pragma unroll
            for (int nt2 = 0; nt2 < 8; ++nt2){
                uint32_t roff = (uint32_t)((nt2*16 + m_local)*PADQ + ks*16 + k_off)*2;
                ldm_x4(bh[nt2], kb + roff);
            }
            #pragma unroll
            for (int nt = 0; nt < 16; ++nt){
                int q = nt >> 1, rs = nt & 1;
                mma16816(s[nt], qf[ks], bh[q][rs], bh[q][rs+2]);
            }
        }

        bool diag = (c == rb);
        float cm0 = -1e30f, cm1 = -1e30f;
        #pragma unroll
        for (int nt = 0; nt < 16; ++nt){
            int cl = nt*8 + colb;
            int r_lo = wid*16 + rA, r_hi = r_lo + 8;
            #pragma unroll
            for (int q = 0; q < 4; q++) s[nt][q] *= 0.125f;
            if (diag){
                if (cl     > r_lo) s[nt][0] = -1e30f;
                if (cl + 1 > r_lo) s[nt][1] = -1e30f;
                if (cl     > r_hi) s[nt][2] = -1e30f;
                if (cl + 1 > r_hi) s[nt][3] = -1e30f;
            }
            cm0 = fmaxf(cm0, fmaxf(s[nt][0], s[nt][1]));
            cm1 = fmaxf(cm1, fmaxf(s[nt][2], s[nt][3]));
        }
        cm0 = fmaxf(cm0, __shfl_xor_sync(0xffffffffu, cm0, 1));
        cm0 = fmaxf(cm0, __shfl_xor_sync(0xffffffffu, cm0, 2));
        cm1 = fmaxf(cm1, __shfl_xor_sync(0xffffffffu, cm1, 1));
        cm1 = fmaxf(cm1, __shfl_xor_sync(0xffffffffu, cm1, 2));
        float mn0 = fmaxf(m0, cm0), mn1 = fmaxf(m1, cm1);
        float al0 = expf(m0 - mn0), al1 = expf(m1 - mn1);
        m0 = mn0; m1 = mn1;

        float ls0 = 0.f, ls1 = 0.f;
        #pragma unroll
        for (int nt = 0; nt < 16; ++nt){
            s[nt][0] = expf(s[nt][0] - mn0);
            s[nt][1] = expf(s[nt][1] - mn0);
            s[nt][2] = expf(s[nt][2] - mn1);
            s[nt][3] = expf(s[nt][3] - mn1);
            ls0 += s[nt][0] + s[nt][1];
            ls1 += s[nt][2] + s[nt][3];
        }
        ls0 += __shfl_xor_sync(0xffffffffu, ls0, 1);
        ls0 += __shfl_xor_sync(0xffffffffu, ls0, 2);
        ls1 += __shfl_xor_sync(0xffffffffu, ls1, 1);
        ls1 += __shfl_xor_sync(0xffffffffu, ls1, 2);
        l0 = l0 * al0 + ls0;
        l1 = l1 * al1 + ls1;

        #pragma unroll
        for (int nt = 0; nt < 8; ++nt){
            oacc[nt][0] *= al0; oacc[nt][1] *= al0;
            oacc[nt][2] *= al1; oacc[nt][3] *= al1;
        }

        uint32_t vb = kb + FL_KV;
        #pragma unroll
        for (int kk = 0; kk < 8; ++kk){
            uint32_t a[4];
            a[0] = pack_h2(s[2*kk][0],   s[2*kk][1]);
            a[1] = pack_h2(s[2*kk][2],   s[2*kk][3]);
            a[2] = pack_h2(s[2*kk+1][0], s[2*kk+1][1]);
            a[3] = pack_h2(s[2*kk+1][2], s[2*kk+1][3]);
            uint32_t bv[4][4];
            #pragma unroll
            for (int g2 = 0; g2 < 4; ++g2){
                uint32_t voff = (uint32_t)((kk*16 + t_row)*PADQ + g2*16 + t_col)*2;
                ldm_x4_t(bv[g2], vb + voff);
            }
            #pragma unroll
            for (int nt = 0; nt < 8; ++nt){
                int g2 = nt >> 1, sub = (nt & 1) * 2;
                mma16816(oacc[nt], a, bv[g2][sub], bv[g2][sub+1]);
            }
        }
    }

    float inv0 = 1.f / l0, inv1 = 1.f / l1;
    #pragma unroll
    for (int nt = 0; nt < 8; ++nt){
        long row = row0 + wid*16 + rA;
        long col = nt*8 + colb;
        size_t idx = (size_t)(obase + row*(long)DD + col);
        store_half2(oh, idx,        oacc[nt][0]*inv0, oacc[nt][1]*inv0);
        store_half2(oh, idx + 8*DD, oacc[nt][2]*inv1, oacc[nt][3]*inv1);
    }
}

// ================= pointwise ================================================
__global__ __launch_bounds__(256) void add_ln_k(float* __restrict__ h,
                                                const __half* __restrict__ delta,
                                                const float* __restrict__ w,
                                                const float* __restrict__ b,
                                                float* __restrict__ out2){
    long t = blockIdx.x;
    int tid = threadIdx.x;
    int j = tid * 4;
    __shared__ float sh[8];
    float4 hv = *(const float4*)(h + t * DD + j);
    __half2 d0 = *(const __half2*)(delta + t * DD + j);
    __half2 d1 = *(const __half2*)(delta + t * DD + j + 2);
    float x[4] = {hv.x + __low2float(d0), hv.y + __high2float(d0),
                  hv.z + __low2float(d1), hv.w + __high2float(d1)};
    float s = x[0] + x[1] + x[2] + x[3];
    float mean = blockSum256(s, sh) * (1.f / DD);
    float sq = 0.f;
    #pragma unroll
    for (int c = 0; c < 4; c++){ float d = x[c] - mean; sq += d * d; }
    float var = blockSum256(sq, sh) * (1.f / DD);
    float inv = rsqrtf(var + 1e-5f);
    float4 o;
    o.x = (x[0]-mean)*inv*w[j+0] + b[j+0];
    o.y = (x[1]-mean)*inv*w[j+1] + b[j+1];
    o.z = (x[2]-mean)*inv*w[j+2] + b[j+2];
    o.w = (x[3]-mean)*inv*w[j+3] + b[j+3];
    size_t idx = (size_t)t * DD + j;
    *(float4*)(h + idx) = o;
    store_half4(g_hh, idx, o);
    if (out2) *(float4*)(out2 + idx) = o;
}

// ================= launch ===================================================
extern "C" void kernel_launch(void* const* d_in, const int* in_sizes, int n_in,
                              void* d_out, int out_size)
{
    const int*   x    = (const int*)  d_in[0];
    const float* tok  = (const float*)d_in[1];
    const float* pos  = (const float*)d_in[2];
    const float* Wq   = (const float*)d_in[3];
    const float* bq   = (const float*)d_in[4];
    const float* Wk   = (const float*)d_in[5];
    const float* bk   = (const float*)d_in[6];
    const float* Wv   = (const float*)d_in[7];
    const float* bv   = (const float*)d_in[8];
    const float* Wo   = (const float*)d_in[9];
    const float* bo   = (const float*)d_in[10];
    const float* ln1w = (const float*)d_in[11];
    const float* ln1b = (const float*)d_in[12];
    const float* ln2w = (const float*)d_in[13];
    const float* ln2b = (const float*)d_in[14];
    const float* W1   = (const float*)d_in[15];
    const float* b1   = (const float*)d_in[16];
    const float* W2   = (const float*)d_in[17];
    const float* b2   = (const float*)d_in[18];
    const float* Wout = (const float*)d_in[19];
    const float* bout = (const float*)d_in[20];
    float* out = (float*)d_out;

    static int attr_set = 0;
    if (!attr_set){
        cudaFuncSetAttribute(gemm_nn, cudaFuncAttributeMaxDynamicSharedMemorySize, GM_SMEM);
        cudaFuncSetAttribute(flash_k, cudaFuncAttributeMaxDynamicSharedMemorySize, FL_SMEM);
        attr_set = 1;
    }

    float *h, *bqkv;
    __half *hh, *qh, *oh, *ffh, *th;
    __half *wqn, *won, *w1n, *w2n, *woutn;
    cudaGetSymbolAddress((void**)&h,    g_h);
    cudaGetSymbolAddress((void**)&bqkv, g_bqkv);
    cudaGetSymbolAddress((void**)&hh,   g_hh);
    cudaGetSymbolAddress((void**)&qh,   g_qkvh);
    cudaGetSymbolAddress((void**)&oh,   g_oh);
    cudaGetSymbolAddress((void**)&ffh,  g_ffh);
    cudaGetSymbolAddress((void**)&th,   g_th);
    cudaGetSymbolAddress((void**)&wqn,  g_wqkvn);
    cudaGetSymbolAddress((void**)&won,  g_wo_n);
    cudaGetSymbolAddress((void**)&w1n,  g_w1_n);
    cudaGetSymbolAddress((void**)&w2n,  g_w2_n);
    cudaGetSymbolAddress((void**)&woutn,g_woutn);

    // --- weight prep: permute/cast only (vectorized) ---
    packbias_k<<<24, 256>>>(bq, bk, bv);
    qkvpack_k<<<1024, 256>>>(Wq, wqn, 0);
    qkvpack_k<<<1024, 256>>>(Wk, wqn, 1);
    qkvpack_k<<<1024, 256>>>(Wv, wqn, 2);
    cast_k<<<1024,  256>>>(Wo,   won);
    cast_k<<<4096,  256>>>(W1,   w1n);
    cast_k<<<4096,  256>>>(W2,   w2n);
    cast_k<<<16000, 256>>>(Wout, woutn);

    embed_k<<<BS, 256>>>(x, tok, pos);

    for (int l = 0; l < LL; l++){
        // QKV: [4096,1024] x [1024,3072] -> fp16
        gemm_nn<<<dim3(BS/128, 3*DD/128), 256, GM_SMEM>>>(
            hh, wqn + (long)l*DD*3*DD, bqkv + (long)l*3*DD,
            0, qh, DD, 3*DD, 3*DD, 2);
        // fused attention
        flash_k<<<dim3(HH*BB, SS/128), 256, FL_SMEM>>>(qh, oh);
        // Wo -> fp16 delta
        gemm_nn<<<dim3(BS/128, DD/128), 256, GM_SMEM>>>(
            oh, won + (long)l*DD*DD, bo + (long)l*DD,
            0, th, DD, DD, DD, 2);
        add_ln_k<<<BS, 256>>>(h, th, ln1w + (long)l*DD, ln1b + (long)l*DD, 0);
        // W1 + GELU -> ff (fp16)
        gemm_nn<<<dim3(BS/128, FFD/128), 256, GM_SMEM>>>(
            hh, w1n + (long)l*DD*FFD, b1 + (long)l*FFD,
            0, ffh, DD, FFD, FFD, 1);
        // W2 -> fp16 delta
        gemm_nn<<<dim3(BS/128, DD/128), 256, GM_SMEM>>>(
            ffh, w2n + (long)l*FFD*DD, b2 + (long)l*DD,
            0, th, FFD, DD, DD, 2);
        add_ln_k<<<BS, 256>>>(h, th, ln2w + (long)l*DD, ln2b + (long)l*DD,
                              (l == LL-1) ? (out + (long)BS*VV) : 0);
    }

    // logits (fp32 out)
    gemm_nn<<<dim3(BS/128, VV/128), 256, GM_SMEM>>>(
        hh, woutn, bout, out, 0, DD, VV, VV, 0);
}

// round 14
// speedup vs baseline: 1.0063x; 1.0016x over previous
#include <cuda_runtime.h>
#include <cuda_fp16.h>
#include <math.h>
#include <stdint.h>

#define LL 2
#define HH 16
#define DD 1024
#define HD 64
#define FFD 4096
#define VV 32000
#define SS 1024
#define BB 4
#define BS (BB*SS)   /* 4096 */

// ================= scratch (device globals) =================================
__device__ float g_h  [(size_t)BS*DD];

__device__ __half g_hh [(size_t)BS*DD];
__device__ __half g_qkvh[(size_t)BS*3*DD];
__device__ __half g_oh [(size_t)BS*DD];
__device__ __half g_ffh[(size_t)BS*FFD];
__device__ __half g_th [(size_t)BS*DD];

__device__ __half g_wqkvn[(size_t)LL*DD*3*DD];   // [L][D][3*D]  (K x N)
__device__ __half g_wo_n [(size_t)LL*DD*DD];
__device__ __half g_w1_n [(size_t)LL*DD*FFD];
__device__ __half g_w2_n [(size_t)LL*FFD*DD];
__device__ __half g_woutn[(size_t)DD*VV];
__device__ float g_bqkv[(size_t)LL*3*DD];

// ================= small helpers ============================================
__device__ __forceinline__ uint32_t smem_to_u32(const void* smem_ptr) {
    uint32_t addr;
    asm("{ .reg .u64 tmp; cvta.to.shared.u64 tmp, %1; cvt.u32.u64 %0, tmp; }"
        : "=r"(addr) : "l"(smem_ptr));
    return addr;
}
__device__ __forceinline__ void cp16(uint32_t d, const void* s){
    asm volatile("cp.async.cg.shared.global [%0], [%1], 16;" :: "r"(d), "l"(s) : "memory");
}
__device__ __forceinline__ void ldm_x4(uint32_t* r, uint32_t addr){
    asm volatile("ldmatrix.sync.aligned.m8n8.x4.shared.b16 {%0,%1,%2,%3}, [%4];"
        : "=r"(r[0]), "=r"(r[1]), "=r"(r[2]), "=r"(r[3]) : "r"(addr));
}
__device__ __forceinline__ void ldm_x4_t(uint32_t* r, uint32_t addr){
    asm volatile("ldmatrix.sync.aligned.m8n8.x4.trans.shared.b16 {%0,%1,%2,%3}, [%4];"
        : "=r"(r[0]), "=r"(r[1]), "=r"(r[2]), "=r"(r[3]) : "r"(addr));
}
__device__ __forceinline__ void mma16816(float* c, const uint32_t* a, uint32_t b0, uint32_t b1){
    asm volatile("mma.sync.aligned.m16n8k16.row.col.f32.f16.f16.f32 "
        "{%0,%1,%2,%3}, {%4,%5,%6,%7}, {%8,%9}, {%0,%1,%2,%3};"
        : "+f"(c[0]), "+f"(c[1]), "+f"(c[2]), "+f"(c[3])
        : "r"(a[0]), "r"(a[1]), "r"(a[2]), "r"(a[3]), "r"(b0), "r"(b1));
}
__device__ __forceinline__ float warpSum(float v){
    #pragma unroll
    for (int o = 16; o > 0; o >>= 1) v += __shfl_xor_sync(0xffffffffu, v, o);
    return v;
}
__device__ __forceinline__ float blockSum256(float v, float* sh){
    int lane = threadIdx.x & 31, wid = threadIdx.x >> 5;
    v = warpSum(v);
    if (lane == 0) sh[wid] = v;
    __syncthreads();
    float r = (threadIdx.x < 8) ? sh[threadIdx.x] : 0.f;
    if (threadIdx.x < 32) { r = warpSum(r); if (threadIdx.x == 0) sh[0] = r; }
    __syncthreads();
    float res = sh[0];
    __syncthreads();
    return res;
}
__device__ __forceinline__ float gelu_f(float x){
    return 0.5f * x * (1.0f + erff(x * 0.70710678118654752f));
}
__device__ __forceinline__ void store_half4(__half* p, size_t idx, float4 v){
    *(__half2*)(p+idx)   = __halves2half2(__float2half_rn(v.x), __float2half_rn(v.y));
    *(__half2*)(p+idx+2) = __halves2half2(__float2half_rn(v.z), __float2half_rn(v.w));
}
__device__ __forceinline__ void store_half2(__half* p, size_t idx, float a, float b){
    *(__half2*)(p+idx) = __halves2half2(__float2half_rn(a), __float2half_rn(b));
}
__device__ __forceinline__ uint32_t pack_h2(float a, float b){
    __half2 h = __halves2half2(__float2half_rn(a), __float2half_rn(b));
    return *(uint32_t*)&h;
}
__device__ __forceinline__ uint4 pack_h8(float4 a, float4 b){
    uint4 u;
    u.x = pack_h2(a.x, a.y); u.y = pack_h2(a.z, a.w);
    u.z = pack_h2(b.x, b.y); u.w = pack_h2(b.z, b.w);
    return u;
}

// ================= prep kernels =============================================
__global__ __launch_bounds__(256) void packbias_k(const float* __restrict__ bq,
                                                  const float* __restrict__ bk,
                                                  const float* __restrict__ bv){
    int i = blockIdx.x*256 + threadIdx.x;
    int l = i / (3*DD), n = i % (3*DD);
    float v = (n < DD) ? bq[l*DD + n] : (n < 2*DD) ? bk[l*DD + n - DD] : bv[l*DD + n - 2*DD];
    g_bqkv[i] = v;
}

// fp32 -> fp16 cast, 32 elems/thread (8 loads batched, MLP=8)
__global__ __launch_bounds__(256) void cast32_k(const float* __restrict__ in,
                                                __half* __restrict__ out){
    size_t i = ((size_t)blockIdx.x*256 + threadIdx.x)*32;
    float4 v[8];
    #pragma unroll
    for (int q = 0; q < 8; q++) v[q] = *(const float4*)(in + i + q*4);
    #pragma unroll
    for (int q = 0; q < 4; q++)
        *(uint4*)(out + i + q*8) = pack_h8(v[2*q], v[2*q+1]);
}

// QKV weight permute+cast: out[l][d][sec*1024 + h*64 + e] = W[l][h][d][e]
// grid.z = sec; 8 elems/thread
__global__ __launch_bounds__(256) void qkvpack_k(const float* __restrict__ Wq,
                                                 const float* __restrict__ Wk,
                                                 const float* __restrict__ Wv,
                                                 __half* __restrict__ out){
    int sec = blockIdx.z;
    const float* W = (sec == 0) ? Wq : (sec == 1) ? Wk : Wv;
    size_t i = (size_t)blockIdx.x*256 + threadIdx.x;  // 262144 total
    int e8 = (int)(i & 7);
    int d  = (int)((i >> 3) & 1023);
    int h  = (int)((i >> 13) & 15);
    int l  = (int)(i >> 17);
    const float* src = W + (((size_t)(l*16 + h)*1024 + d)*64 + e8*8);
    float4 a = *(const float4*)(src);
    float4 b = *(const float4*)(src + 4);
    size_t o = ((size_t)(l*1024 + d)*3072) + sec*1024 + h*64 + e8*8;
    *(uint4*)(out + o) = pack_h8(a, b);
}

__global__ __launch_bounds__(256) void embed_k(const int* __restrict__ x,
                                               const float* __restrict__ tok,
                                               const float* __restrict__ pos){
    int t = blockIdx.x;
    int s = t & (SS - 1);
    int id = x[t];
    int j = threadIdx.x * 4;
    float4 a = *(const float4*)(tok + (size_t)id * DD + j);
    float4 p = *(const float4*)(pos + (size_t)s  * DD + j);
    float4 r; r.x = a.x + p.x; r.y = a.y + p.y; r.z = a.z + p.z; r.w = a.w + p.w;
    size_t idx = (size_t)t * DD + j;
    *(float4*)(g_h + idx) = r;
    store_half4(g_hh, idx, r);
}

// ================= fp16 NN GEMM via mma.sync ================================
// (round-11 proven config: 256 thr, 8 warps 32x64, double buffer)
#define PADK 40
#define PADN 136
#define ASZ (128*PADK*2)   /* 10240 */
#define BSZ (32*PADN*2)    /* 8704  */
#define GBUF (ASZ+BSZ)     /* 18944 */
#define GM_SMEM (2*GBUF)   /* 37888 */
__global__ __launch_bounds__(256, 2) void gemm_nn(
    const __half* __restrict__ A, const __half* __restrict__ B,
    const float* __restrict__ bias,
    float* __restrict__ Cf, __half* __restrict__ Ch,
    int K_, int ldb, int ldc, int op)
{
    extern __shared__ char smem[];
    uint32_t sb = smem_to_u32(smem);
    int tid = threadIdx.x, lane = tid & 31, wid = tid >> 5;
    int wm = wid & 3, wn = wid >> 2;
    long row0 = (long)blockIdx.x * 128;
    long col0 = (long)blockIdx.y * 128;

    float acc[2][8][4];
    #pragma unroll
    for (int i = 0; i < 2; i++)
        #pragma unroll
        for (int j = 0; j < 8; j++)
            #pragma unroll
            for (int q = 0; q < 4; q++) acc[i][j][q] = 0.f;

    auto load_chunk = [&](int c, int buf){
        long k0 = (long)c * 32;
        uint32_t base = sb + (uint32_t)buf * GBUF;
        #pragma unroll
        for (int i = tid; i < 512; i += 256){
            int r = i >> 2, seg = (i & 3) * 8;
            cp16(base + (uint32_t)(r*PADK + seg)*2, A + (row0 + r)*(long)K_ + k0 + seg);
        }
        #pragma unroll
        for (int i = tid; i < 512; i += 256){
            int r = i >> 4, u = (i & 15) * 8;
            cp16(base + ASZ + (uint32_t)(r*PADN + u)*2, B + (k0 + r)*(long)ldb + col0 + u);
        }
        asm volatile("cp.async.commit_group;" ::: "memory");
    };

    const int NC = K_ >> 5;
    load_chunk(0, 0);

    int m_local = (lane & 7) | (lane & 8);
    int k_off = (lane >> 4) * 8;
    int t_row = lane & 15, t_col = (lane >> 4) * 8;

    for (int c = 0; c < NC; ++c){
        int buf = c & 1;
        asm volatile("cp.async.wait_group 0;" ::: "memory");
        __syncthreads();
        if (c + 1 < NC) load_chunk(c + 1, buf ^ 1);

        uint32_t base = sb + (uint32_t)buf * GBUF;
        #pragma unroll
        for (int ks = 0; ks < 2; ++ks){
            uint32_t a_h[2][4];
            #pragma unroll
            for (int am = 0; am < 2; ++am){
                uint32_t roff = (uint32_t)((wm*32 + am*16 + m_local) * PADK + ks*16 + k_off) * 2;
                ldm_x4(a_h[am], base + roff);
            }
            uint32_t bt[4][4];
            #pragma unroll
            for (int g2 = 0; g2 < 4; ++g2){
                uint32_t voff = (uint32_t)((ks*16 + t_row)*PADN + wn*64 + g2*16 + t_col) * 2;
                ldm_x4_t(bt[g2], base + ASZ + voff);
            }
            #pragma unroll
            for (int mt = 0; mt < 2; ++mt)
                #pragma unroll
                for (int nt = 0; nt < 8; ++nt){
                    int g2 = nt >> 1, sub = (nt & 1) * 2;
                    mma16816(acc[mt][nt], a_h[mt], bt[g2][sub], bt[g2][sub+1]);
                }
        }
    }

    #pragma unroll
    for (int mt = 0; mt < 2; ++mt){
        #pragma unroll
        for (int nt = 0; nt < 8; ++nt){
            long row = row0 + wm*32 + mt*16 + (lane >> 2);
            long col = col0 + wn*64 + nt*8 + (lane & 3)*2;
            float b0 = bias[col], b1 = bias[col+1];
            float v0 = acc[mt][nt][0] + b0, v1 = acc[mt][nt][1] + b1;
            float v2 = acc[mt][nt][2] + b0, v3 = acc[mt][nt][3] + b1;
            if (op == 0){
                *(float2*)(Cf + row*(long)ldc + col)     = make_float2(v0, v1);
                *(float2*)(Cf + (row+8)*(long)ldc + col) = make_float2(v2, v3);
            } else if (op == 1){
                store_half2(Ch, (size_t)(row*(long)ldc + col),     gelu_f(v0), gelu_f(v1));
                store_half2(Ch, (size_t)((row+8)*(long)ldc + col), gelu_f(v2), gelu_f(v3));
            } else {
                store_half2(Ch, (size_t)(row*(long)ldc + col),     v0, v1);
                store_half2(Ch, (size_t)((row+8)*(long)ldc + col), v2, v3);
            }
        }
    }
}

// ================= fused flash attention (64-key chunks, occ 2) =============
#define PADQ 72
#define FL_Q   (128*PADQ*2)              /* 18432 */
#define FL_KV  (64*PADQ*2)               /* 9216  */
#define FL_BUF (2*FL_KV)                 /* 18432 */
#define FL_SMEM (FL_Q + 2*FL_BUF)        /* 55296 -> 2 CTAs/SM */
__global__ __launch_bounds__(256, 2) void flash_k(
    const __half* __restrict__ qkvh, __half* __restrict__ oh)
{
    extern __shared__ char smem[];
    uint32_t sb = smem_to_u32(smem);
    int z = blockIdx.x; int b = z & 3, hd = z >> 2;
    int rb = blockIdx.y;
    long qbase = (long)b*SS*(3*DD) + hd*HD;
    long kbase = qbase + DD;
    long vbase = qbase + 2*DD;
    long obase = (long)b*SS*DD + hd*HD;
    int tid = threadIdx.x, lane = tid & 31, wid = tid >> 5;
    long row0 = (long)rb * 128;

    // Q tile 128 x 64
    #pragma unroll
    for (int i = tid; i < 1024; i += 256){
        int r = i >> 3, u = (i & 7) * 8;
        cp16(sb + (uint32_t)(r*PADQ + u)*2, qkvh + qbase + (row0 + r)*(long)(3*DD) + u);
    }
    asm volatile("cp.async.commit_group;" ::: "memory");

    // K/V chunks of 64 keys
    auto load_kv = [&](int c, int buf){
        uint32_t base = sb + FL_Q + (uint32_t)buf * FL_BUF;
        long k0 = (long)c * 64;
        #pragma unroll
        for (int i = tid; i < 512; i += 256){
            int r = i >> 3, u = (i & 7) * 8;
            uint32_t soff = (uint32_t)(r*PADQ + u)*2;
            cp16(base + soff,         qkvh + kbase + (k0 + r)*(long)(3*DD) + u);
            cp16(base + FL_KV + soff, qkvh + vbase + (k0 + r)*(long)(3*DD) + u);
        }
        asm volatile("cp.async.commit_group;" ::: "memory");
    };
    const int nchunks = 2*rb + 2;
    load_kv(0, 0);
    asm volatile("cp.async.wait_group 0;" ::: "memory");
    __syncthreads();

    int m_local = (lane & 7) | (lane & 8);
    int k_off = (lane >> 4) * 8;
    int t_row = lane & 15, t_col = (lane >> 4) * 8;
    int rA = lane >> 2;
    int colb = (lane & 3) * 2;

    uint32_t qf[4][4];
    #pragma unroll
    for (int ks = 0; ks < 4; ++ks){
        uint32_t roff = (uint32_t)((wid*16 + m_local)*PADQ + ks*16 + k_off)*2;
        ldm_x4(qf[ks], sb + roff);
    }

    float oacc[8][4];
    #pragma unroll
    for (int j = 0; j < 8; j++)
        #pragma unroll
        for (int q = 0; q < 4; q++) oacc[j][q] = 0.f;
    float m0 = -1e30f, m1 = -1e30f, l0 = 0.f, l1 = 0.f;

    for (int c = 0; c < nchunks; ++c){
        int buf = c & 1;
        if (c > 0){
            asm volatile("cp.async.wait_group 0;" ::: "memory");
            __syncthreads();
        }
        if (c + 1 < nchunks) load_kv(c + 1, buf ^ 1);
        uint32_t kb = sb + FL_Q + (uint32_t)buf * FL_BUF;

        // S = Q @ K^T : 16 rows x 64 keys per warp
        float s[8][4];
        #pragma unroll
        for (int j = 0; j < 8; j++)
            #pragma unroll
            for (int q = 0; q < 4; q++) s[j][q] = 0.f;
        #pragma unroll
        for (int ks = 0; ks < 4; ++ks){
            uint32_t bh[4][4];
            #pragma unroll
            for (int nt2 = 0; nt2 < 4; ++nt2){
                uint32_t roff = (uint32_t)((nt2*16 + m_local)*PADQ + ks*16 + k_off)*2;
                ldm_x4(bh[nt2], kb + roff);
            }
            #pragma unroll
            for (int nt = 0; nt < 8; ++nt){
                int q = nt >> 1, rs = nt & 1;
                mma16816(s[nt], qf[ks], bh[q][rs], bh[q][rs+2]);
            }
        }

        // scale + causal mask (global compare; only active for c >= 2*rb)
        bool maskc = (c >= 2*rb);
        float cm0 = -1e30f, cm1 = -1e30f;
        long gr_lo = row0 + wid*16 + rA, gr_hi = gr_lo + 8;
        #pragma unroll
        for (int nt = 0; nt < 8; ++nt){
            long gcol = (long)c*64 + nt*8 + colb;
            #pragma unroll
            for (int q = 0; q < 4; q++) s[nt][q] *= 0.125f;
            if (maskc){
                if (gcol     > gr_lo) s[nt][0] = -1e30f;
                if (gcol + 1 > gr_lo) s[nt][1] = -1e30f;
                if (gcol     > gr_hi) s[nt][2] = -1e30f;
                if (gcol + 1 > gr_hi) s[nt][3] = -1e30f;
            }
            cm0 = fmaxf(cm0, fmaxf(s[nt][0], s[nt][1]));
            cm1 = fmaxf(cm1, fmaxf(s[nt][2], s[nt][3]));
        }
        cm0 = fmaxf(cm0, __shfl_xor_sync(0xffffffffu, cm0, 1));
        cm0 = fmaxf(cm0, __shfl_xor_sync(0xffffffffu, cm0, 2));
        cm1 = fmaxf(cm1, __shfl_xor_sync(0xffffffffu, cm1, 1));
        cm1 = fmaxf(cm1, __shfl_xor_sync(0xffffffffu, cm1, 2));
        float mn0 = fmaxf(m0, cm0), mn1 = fmaxf(m1, cm1);
        float al0 = expf(m0 - mn0), al1 = expf(m1 - mn1);
        m0 = mn0; m1 = mn1;

        float ls0 = 0.f, ls1 = 0.f;
        #pragma unroll
        for (int nt = 0; nt < 8; ++nt){
            s[nt][0] = expf(s[nt][0] - mn0);
            s[nt][1] = expf(s[nt][1] - mn0);
            s[nt][2] = expf(s[nt][2] - mn1);
            s[nt][3] = expf(s[nt][3] - mn1);
            ls0 += s[nt][0] + s[nt][1];
            ls1 += s[nt][2] + s[nt][3];
        }
        ls0 += __shfl_xor_sync(0xffffffffu, ls0, 1);
        ls0 += __shfl_xor_sync(0xffffffffu, ls0, 2);
        ls1 += __shfl_xor_sync(0xffffffffu, ls1, 1);
        ls1 += __shfl_xor_sync(0xffffffffu, ls1, 2);
        l0 = l0 * al0 + ls0;
        l1 = l1 * al1 + ls1;

        #pragma unroll
        for (int nt = 0; nt < 8; ++nt){
            oacc[nt][0] *= al0; oacc[nt][1] *= al0;
            oacc[nt][2] *= al1; oacc[nt][3] *= al1;
        }

        // O += P @ V  (64 keys = 4 k-steps)
        uint32_t vb = kb + FL_KV;
        #pragma unroll
        for (int kk = 0; kk < 4; ++kk){
            uint32_t a[4];
            a[0] = pack_h2(s[2*kk][0],   s[2*kk][1]);
            a[1] = pack_h2(s[2*kk][2],   s[2*kk][3]);
            a[2] = pack_h2(s[2*kk+1][0], s[2*kk+1][1]);
            a[3] = pack_h2(s[2*kk+1][2], s[2*kk+1][3]);
            uint32_t bv[4][4];
            #pragma unroll
            for (int g2 = 0; g2 < 4; ++g2){
                uint32_t voff = (uint32_t)((kk*16 + t_row)*PADQ + g2*16 + t_col)*2;
                ldm_x4_t(bv[g2], vb + voff);
            }
            #pragma unroll
            for (int nt = 0; nt < 8; ++nt){
                int g2 = nt >> 1, sub = (nt & 1) * 2;
                mma16816(oacc[nt], a, bv[g2][sub], bv[g2][sub+1]);
            }
        }
    }

    float inv0 = 1.f / l0, inv1 = 1.f / l1;
    #pragma unroll
    for (int nt = 0; nt < 8; ++nt){
        long row = row0 + wid*16 + rA;
        long col = nt*8 + colb;
        size_t idx = (size_t)(obase + row*(long)DD + col);
        store_half2(oh, idx,        oacc[nt][0]*inv0, oacc[nt][1]*inv0);
        store_half2(oh, idx + 8*DD, oacc[nt][2]*inv1, oacc[nt][3]*inv1);
    }
}

// ================= pointwise ================================================
__global__ __launch_bounds__(256) void add_ln_k(float* __restrict__ h,
                                                const __half* __restrict__ delta,
                                                const float* __restrict__ w,
                                                const float* __restrict__ b,
                                                float* __restrict__ out2){
    long t = blockIdx.x;
    int tid = threadIdx.x;
    int j = tid * 4;
    __shared__ float sh[8];
    float4 hv = *(const float4*)(h + t * DD + j);
    __half2 d0 = *(const __half2*)(delta + t * DD + j);
    __half2 d1 = *(const __half2*)(delta + t * DD + j + 2);
    float x[4] = {hv.x + __low2float(d0), hv.y + __high2float(d0),
                  hv.z + __low2float(d1), hv.w + __high2float(d1)};
    float s = x[0] + x[1] + x[2] + x[3];
    float mean = blockSum256(s, sh) * (1.f / DD);
    float sq = 0.f;
    #pragma unroll
    for (int c = 0; c < 4; c++){ float d = x[c] - mean; sq += d * d; }
    float var = blockSum256(sq, sh) * (1.f / DD);
    float inv = rsqrtf(var + 1e-5f);
    float4 o;
    o.x = (x[0]-mean)*inv*w[j+0] + b[j+0];
    o.y = (x[1]-mean)*inv*w[j+1] + b[j+1];
    o.z = (x[2]-mean)*inv*w[j+2] + b[j+2];
    o.w = (x[3]-mean)*inv*w[j+3] + b[j+3];
    size_t idx = (size_t)t * DD + j;
    *(float4*)(h + idx) = o;
    store_half4(g_hh, idx, o);
    if (out2) *(float4*)(out2 + idx) = o;
}

// ================= launch ===================================================
extern "C" void kernel_launch(void* const* d_in, const int* in_sizes, int n_in,
                              void* d_out, int out_size)
{
    const int*   x    = (const int*)  d_in[0];
    const float* tok  = (const float*)d_in[1];
    const float* pos  = (const float*)d_in[2];
    const float* Wq   = (const float*)d_in[3];
    const float* bq   = (const float*)d_in[4];
    const float* Wk   = (const float*)d_in[5];
    const float* bk   = (const float*)d_in[6];
    const float* Wv   = (const float*)d_in[7];
    const float* bv   = (const float*)d_in[8];
    const float* Wo   = (const float*)d_in[9];
    const float* bo   = (const float*)d_in[10];
    const float* ln1w = (const float*)d_in[11];
    const float* ln1b = (const float*)d_in[12];
    const float* ln2w = (const float*)d_in[13];
    const float* ln2b = (const float*)d_in[14];
    const float* W1   = (const float*)d_in[15];
    const float* b1   = (const float*)d_in[16];
    const float* W2   = (const float*)d_in[17];
    const float* b2   = (const float*)d_in[18];
    const float* Wout = (const float*)d_in[19];
    const float* bout = (const float*)d_in[20];
    float* out = (float*)d_out;

    static int attr_set = 0;
    if (!attr_set){
        cudaFuncSetAttribute(gemm_nn, cudaFuncAttributeMaxDynamicSharedMemorySize, GM_SMEM);
        cudaFuncSetAttribute(flash_k, cudaFuncAttributeMaxDynamicSharedMemorySize, FL_SMEM);
        attr_set = 1;
    }

    float *h, *bqkv;
    __half *hh, *qh, *oh, *ffh, *th;
    __half *wqn, *won, *w1n, *w2n, *woutn;
    cudaGetSymbolAddress((void**)&h,    g_h);
    cudaGetSymbolAddress((void**)&bqkv, g_bqkv);
    cudaGetSymbolAddress((void**)&hh,   g_hh);
    cudaGetSymbolAddress((void**)&qh,   g_qkvh);
    cudaGetSymbolAddress((void**)&oh,   g_oh);
    cudaGetSymbolAddress((void**)&ffh,  g_ffh);
    cudaGetSymbolAddress((void**)&th,   g_th);
    cudaGetSymbolAddress((void**)&wqn,  g_wqkvn);
    cudaGetSymbolAddress((void**)&won,  g_wo_n);
    cudaGetSymbolAddress((void**)&w1n,  g_w1_n);
    cudaGetSymbolAddress((void**)&w2n,  g_w2_n);
    cudaGetSymbolAddress((void**)&woutn,g_woutn);

    // --- weight prep (vectorized, merged) ---
    packbias_k<<<24, 256>>>(bq, bk, bv);
    qkvpack_k<<<dim3(1024,1,3), 256>>>(Wq, Wk, Wv, wqn);
    cast32_k<<<256,  256>>>(Wo,   won);
    cast32_k<<<1024, 256>>>(W1,   w1n);
    cast32_k<<<1024, 256>>>(W2,   w2n);
    cast32_k<<<4000, 256>>>(Wout, woutn);

    embed_k<<<BS, 256>>>(x, tok, pos);

    for (int l = 0; l < LL; l++){
        gemm_nn<<<dim3(BS/128, 3*DD/128), 256, GM_SMEM>>>(
            hh, wqn + (long)l*DD*3*DD, bqkv + (long)l*3*DD,
            0, qh, DD, 3*DD, 3*DD, 2);
        flash_k<<<dim3(HH*BB, SS/128), 256, FL_SMEM>>>(qh, oh);
        gemm_nn<<<dim3(BS/128, DD/128), 256, GM_SMEM>>>(
            oh, won + (long)l*DD*DD, bo + (long)l*DD,
            0, th, DD, DD, DD, 2);
        add_ln_k<<<BS, 256>>>(h, th, ln1w + (long)l*DD, ln1b + (long)l*DD, 0);
        gemm_nn<<<dim3(BS/128, FFD/128), 256, GM_SMEM>>>(
            hh, w1n + (long)l*DD*FFD, b1 + (long)l*FFD,
            0, ffh, DD, FFD, FFD, 1);
        gemm_nn<<<dim3(BS/128, DD/128), 256, GM_SMEM>>>(
            ffh, w2n + (long)l*FFD*DD, b2 + (long)l*DD,
            0, th, FFD, DD, DD, 2);
        add_ln_k<<<BS, 256>>>(h, th, ln2w + (long)l*DD, ln2b + (long)l*DD,
                              (l == LL-1) ? (out + (long)BS*VV) : 0);
    }

    gemm_nn<<<dim3(BS/128, VV/128), 256, GM_SMEM>>>(
        hh, woutn, bout, out, 0, DD, VV, VV, 0);
}

// round 15
// speedup vs baseline: 1.0234x; 1.0170x over previous
#include <cuda_runtime.h>
#include <cuda_fp16.h>
#include <math.h>
#include <stdint.h>

#define LL 2
#define HH 16
#define DD 1024
#define HD 64
#define FFD 4096
#define VV 32000
#define SS 1024
#define BB 4
#define BS (BB*SS)   /* 4096 */

// ================= scratch (device globals) =================================
__device__ float g_h  [(size_t)BS*DD];

__device__ __half g_hh [(size_t)BS*DD];
__device__ __half g_qkvh[(size_t)BS*3*DD];
__device__ __half g_oh [(size_t)BS*DD];
__device__ __half g_ffh[(size_t)BS*FFD];
__device__ __half g_th [(size_t)BS*DD];

__device__ __half g_wqkvn[(size_t)LL*DD*3*DD];   // [L][D][3*D]  (K x N)
__device__ __half g_wo_n [(size_t)LL*DD*DD];
__device__ __half g_w1_n [(size_t)LL*DD*FFD];
__device__ __half g_w2_n [(size_t)LL*FFD*DD];
__device__ __half g_woutn[(size_t)DD*VV];
__device__ float g_bqkv[(size_t)LL*3*DD];

// ================= small helpers ============================================
__device__ __forceinline__ uint32_t smem_to_u32(const void* smem_ptr) {
    uint32_t addr;
    asm("{ .reg .u64 tmp; cvta.to.shared.u64 tmp, %1; cvt.u32.u64 %0, tmp; }"
        : "=r"(addr) : "l"(smem_ptr));
    return addr;
}
__device__ __forceinline__ void cp16(uint32_t d, const void* s){
    asm volatile("cp.async.cg.shared.global [%0], [%1], 16;" :: "r"(d), "l"(s) : "memory");
}
__device__ __forceinline__ void ldm_x4(uint32_t* r, uint32_t addr){
    asm volatile("ldmatrix.sync.aligned.m8n8.x4.shared.b16 {%0,%1,%2,%3}, [%4];"
        : "=r"(r[0]), "=r"(r[1]), "=r"(r[2]), "=r"(r[3]) : "r"(addr));
}
__device__ __forceinline__ void ldm_x4_t(uint32_t* r, uint32_t addr){
    asm volatile("ldmatrix.sync.aligned.m8n8.x4.trans.shared.b16 {%0,%1,%2,%3}, [%4];"
        : "=r"(r[0]), "=r"(r[1]), "=r"(r[2]), "=r"(r[3]) : "r"(addr));
}
__device__ __forceinline__ void mma16816(float* c, const uint32_t* a, uint32_t b0, uint32_t b1){
    asm volatile("mma.sync.aligned.m16n8k16.row.col.f32.f16.f16.f32 "
        "{%0,%1,%2,%3}, {%4,%5,%6,%7}, {%8,%9}, {%0,%1,%2,%3};"
        : "+f"(c[0]), "+f"(c[1]), "+f"(c[2]), "+f"(c[3])
        : "r"(a[0]), "r"(a[1]), "r"(a[2]), "r"(a[3]), "r"(b0), "r"(b1));
}
__device__ __forceinline__ float warpSum(float v){
    #pragma unroll
    for (int o = 16; o > 0; o >>= 1) v += __shfl_xor_sync(0xffffffffu, v, o);
    return v;
}
__device__ __forceinline__ float blockSum256(float v, float* sh){
    int lane = threadIdx.x & 31, wid = threadIdx.x >> 5;
    v = warpSum(v);
    if (lane == 0) sh[wid] = v;
    __syncthreads();
    float r = (threadIdx.x < 8) ? sh[threadIdx.x] : 0.f;
    if (threadIdx.x < 32) { r = warpSum(r); if (threadIdx.x == 0) sh[0] = r; }
    __syncthreads();
    float res = sh[0];
    __syncthreads();
    return res;
}
__device__ __forceinline__ float gelu_f(float x){
    return 0.5f * x * (1.0f + erff(x * 0.70710678118654752f));
}
__device__ __forceinline__ void store_half4(__half* p, size_t idx, float4 v){
    *(__half2*)(p+idx)   = __halves2half2(__float2half_rn(v.x), __float2half_rn(v.y));
    *(__half2*)(p+idx+2) = __halves2half2(__float2half_rn(v.z), __float2half_rn(v.w));
}
__device__ __forceinline__ void store_half2(__half* p, size_t idx, float a, float b){
    *(__half2*)(p+idx) = __halves2half2(__float2half_rn(a), __float2half_rn(b));
}
__device__ __forceinline__ uint32_t pack_h2(float a, float b){
    __half2 h = __halves2half2(__float2half_rn(a), __float2half_rn(b));
    return *(uint32_t*)&h;
}
__device__ __forceinline__ uint4 pack_h8(float4 a, float4 b){
    uint4 u;
    u.x = pack_h2(a.x, a.y); u.y = pack_h2(a.z, a.w);
    u.z = pack_h2(b.x, b.y); u.w = pack_h2(b.z, b.w);
    return u;
}

// ================= prep kernels =============================================
__global__ __launch_bounds__(256) void packbias_k(const float* __restrict__ bq,
                                                  const float* __restrict__ bk,
                                                  const float* __restrict__ bv){
    int i = blockIdx.x*256 + threadIdx.x;
    int l = i / (3*DD), n = i % (3*DD);
    float v = (n < DD) ? bq[l*DD + n] : (n < 2*DD) ? bk[l*DD + n - DD] : bv[l*DD + n - 2*DD];
    g_bqkv[i] = v;
}

// fp32 -> fp16 cast, 32 elems/thread (8 loads batched, MLP=8)
__global__ __launch_bounds__(256) void cast32_k(const float* __restrict__ in,
                                                __half* __restrict__ out){
    size_t i = ((size_t)blockIdx.x*256 + threadIdx.x)*32;
    float4 v[8];
    #pragma unroll
    for (int q = 0; q < 8; q++) v[q] = *(const float4*)(in + i + q*4);
    #pragma unroll
    for (int q = 0; q < 4; q++)
        *(uint4*)(out + i + q*8) = pack_h8(v[2*q], v[2*q+1]);
}

// QKV weight permute+cast: out[l][d][sec*1024 + h*64 + e] = W[l][h][d][e]
__global__ __launch_bounds__(256) void qkvpack_k(const float* __restrict__ Wq,
                                                 const float* __restrict__ Wk,
                                                 const float* __restrict__ Wv,
                                                 __half* __restrict__ out){
    int sec = blockIdx.z;
    const float* W = (sec == 0) ? Wq : (sec == 1) ? Wk : Wv;
    size_t i = (size_t)blockIdx.x*256 + threadIdx.x;  // 262144 total
    int e8 = (int)(i & 7);
    int d  = (int)((i >> 3) & 1023);
    int h  = (int)((i >> 13) & 15);
    int l  = (int)(i >> 17);
    const float* src = W + (((size_t)(l*16 + h)*1024 + d)*64 + e8*8);
    float4 a = *(const float4*)(src);
    float4 b = *(const float4*)(src + 4);
    size_t o = ((size_t)(l*1024 + d)*3072) + sec*1024 + h*64 + e8*8;
    *(uint4*)(out + o) = pack_h8(a, b);
}

__global__ __launch_bounds__(256) void embed_k(const int* __restrict__ x,
                                               const float* __restrict__ tok,
                                               const float* __restrict__ pos){
    int t = blockIdx.x;
    int s = t & (SS - 1);
    int id = x[t];
    int j = threadIdx.x * 4;
    float4 a = *(const float4*)(tok + (size_t)id * DD + j);
    float4 p = *(const float4*)(pos + (size_t)s  * DD + j);
    float4 r; r.x = a.x + p.x; r.y = a.y + p.y; r.z = a.z + p.z; r.w = a.w + p.w;
    size_t idx = (size_t)t * DD + j;
    *(float4*)(g_h + idx) = r;
    store_half4(g_hh, idx, r);
}

// ================= fp16 NN GEMM via mma.sync ================================
#define PADK 40
#define PADN 136
#define ASZ (128*PADK*2)   /* 10240 */
#define BSZ (32*PADN*2)    /* 8704  */
#define GBUF (ASZ+BSZ)     /* 18944 */
#define GM_SMEM (2*GBUF)   /* 37888 */
__global__ __launch_bounds__(256, 2) void gemm_nn(
    const __half* __restrict__ A, const __half* __restrict__ B,
    const float* __restrict__ bias,
    float* __restrict__ Cf, __half* __restrict__ Ch,
    int K_, int ldb, int ldc, int op)
{
    extern __shared__ char smem[];
    uint32_t sb = smem_to_u32(smem);
    int tid = threadIdx.x, lane = tid & 31, wid = tid >> 5;
    int wm = wid & 3, wn = wid >> 2;
    long row0 = (long)blockIdx.x * 128;
    long col0 = (long)blockIdx.y * 128;

    float acc[2][8][4];
    #pragma unroll
    for (int i = 0; i < 2; i++)
        #pragma unroll
        for (int j = 0; j < 8; j++)
            #pragma unroll
            for (int q = 0; q < 4; q++) acc[i][j][q] = 0.f;

    auto load_chunk = [&](int c, int buf){
        long k0 = (long)c * 32;
        uint32_t base = sb + (uint32_t)buf * GBUF;
        #pragma unroll
        for (int i = tid; i < 512; i += 256){
            int r = i >> 2, seg = (i & 3) * 8;
            cp16(base + (uint32_t)(r*PADK + seg)*2, A + (row0 + r)*(long)K_ + k0 + seg);
        }
        #pragma unroll
        for (int i = tid; i < 512; i += 256){
            int r = i >> 4, u = (i & 15) * 8;
            cp16(base + ASZ + (uint32_t)(r*PADN + u)*2, B + (k0 + r)*(long)ldb + col0 + u);
        }
        asm volatile("cp.async.commit_group;" ::: "memory");
    };

    const int NC = K_ >> 5;
    load_chunk(0, 0);

    int m_local = (lane & 7) | (lane & 8);
    int k_off = (lane >> 4) * 8;
    int t_row = lane & 15, t_col = (lane >> 4) * 8;

    for (int c = 0; c < NC; ++c){
        int buf = c & 1;
        asm volatile("cp.async.wait_group 0;" ::: "memory");
        __syncthreads();
        if (c + 1 < NC) load_chunk(c + 1, buf ^ 1);

        uint32_t base = sb + (uint32_t)buf * GBUF;
        #pragma unroll
        for (int ks = 0; ks < 2; ++ks){
            uint32_t a_h[2][4];
            #pragma unroll
            for (int am = 0; am < 2; ++am){
                uint32_t roff = (uint32_t)((wm*32 + am*16 + m_local) * PADK + ks*16 + k_off) * 2;
                ldm_x4(a_h[am], base + roff);
            }
            uint32_t bt[4][4];
            #pragma unroll
            for (int g2 = 0; g2 < 4; ++g2){
                uint32_t voff = (uint32_t)((ks*16 + t_row)*PADN + wn*64 + g2*16 + t_col) * 2;
                ldm_x4_t(bt[g2], base + ASZ + voff);
            }
            #pragma unroll
            for (int mt = 0; mt < 2; ++mt)
                #pragma unroll
                for (int nt = 0; nt < 8; ++nt){
                    int g2 = nt >> 1, sub = (nt & 1) * 2;
                    mma16816(acc[mt][nt], a_h[mt], bt[g2][sub], bt[g2][sub+1]);
                }
        }
    }

    #pragma unroll
    for (int mt = 0; mt < 2; ++mt){
        #pragma unroll
        for (int nt = 0; nt < 8; ++nt){
            long row = row0 + wm*32 + mt*16 + (lane >> 2);
            long col = col0 + wn*64 + nt*8 + (lane & 3)*2;
            float b0 = bias[col], b1 = bias[col+1];
            float v0 = acc[mt][nt][0] + b0, v1 = acc[mt][nt][1] + b1;
            float v2 = acc[mt][nt][2] + b0, v3 = acc[mt][nt][3] + b1;
            if (op == 0){
                *(float2*)(Cf + row*(long)ldc + col)     = make_float2(v0, v1);
                *(float2*)(Cf + (row+8)*(long)ldc + col) = make_float2(v2, v3);
            } else if (op == 1){
                store_half2(Ch, (size_t)(row*(long)ldc + col),     gelu_f(v0), gelu_f(v1));
                store_half2(Ch, (size_t)((row+8)*(long)ldc + col), gelu_f(v2), gelu_f(v3));
            } else {
                store_half2(Ch, (size_t)(row*(long)ldc + col),     v0, v1);
                store_half2(Ch, (size_t)((row+8)*(long)ldc + col), v2, v3);
            }
        }
    }
}

// ================= fused flash attention (128-key chunks) ===================
#define PADQ 72
#define FL_Q   (128*PADQ*2)              /* 18432 */
#define FL_KV  (128*PADQ*2)
#define FL_BUF (2*FL_KV)                 /* 36864 */
#define FL_SMEM (FL_Q + 2*FL_BUF)        /* 92160 */
__global__ __launch_bounds__(256, 1) void flash_k(
    const __half* __restrict__ qkvh, __half* __restrict__ oh)
{
    extern __shared__ char smem[];
    uint32_t sb = smem_to_u32(smem);
    int z = blockIdx.x; int b = z & 3, hd = z >> 2;
    int rb = blockIdx.y;
    long qbase = (long)b*SS*(3*DD) + hd*HD;
    long kbase = qbase + DD;
    long vbase = qbase + 2*DD;
    long obase = (long)b*SS*DD + hd*HD;
    int tid = threadIdx.x, lane = tid & 31, wid = tid >> 5;
    long row0 = (long)rb * 128;

    #pragma unroll
    for (int i = tid; i < 1024; i += 256){
        int r = i >> 3, u = (i & 7) * 8;
        cp16(sb + (uint32_t)(r*PADQ + u)*2, qkvh + qbase + (row0 + r)*(long)(3*DD) + u);
    }
    asm volatile("cp.async.commit_group;" ::: "memory");

    auto load_kv = [&](int c, int buf){
        uint32_t base = sb + FL_Q + (uint32_t)buf * FL_BUF;
        long k0 = (long)c * 128;
        #pragma unroll
        for (int i = tid; i < 1024; i += 256){
            int r = i >> 3, u = (i & 7) * 8;
            uint32_t soff = (uint32_t)(r*PADQ + u)*2;
            cp16(base + soff,         qkvh + kbase + (k0 + r)*(long)(3*DD) + u);
            cp16(base + FL_KV + soff, qkvh + vbase + (k0 + r)*(long)(3*DD) + u);
        }
        asm volatile("cp.async.commit_group;" ::: "memory");
    };
    const int nchunks = rb + 1;
    load_kv(0, 0);
    asm volatile("cp.async.wait_group 0;" ::: "memory");
    __syncthreads();

    int m_local = (lane & 7) | (lane & 8);
    int k_off = (lane >> 4) * 8;
    int t_row = lane & 15, t_col = (lane >> 4) * 8;
    int rA = lane >> 2;
    int colb = (lane & 3) * 2;

    uint32_t qf[4][4];
    #pragma unroll
    for (int ks = 0; ks < 4; ++ks){
        uint32_t roff = (uint32_t)((wid*16 + m_local)*PADQ + ks*16 + k_off)*2;
        ldm_x4(qf[ks], sb + roff);
    }

    float oacc[8][4];
    #pragma unroll
    for (int j = 0; j < 8; j++)
        #pragma unroll
        for (int q = 0; q < 4; q++) oacc[j][q] = 0.f;
    float m0 = -1e30f, m1 = -1e30f, l0 = 0.f, l1 = 0.f;

    for (int c = 0; c < nchunks; ++c){
        int buf = c & 1;
        if (c > 0){
            asm volatile("cp.async.wait_group 0;" ::: "memory");
            __syncthreads();
        }
        if (c + 1 < nchunks) load_kv(c + 1, buf ^ 1);
        uint32_t kb = sb + FL_Q + (uint32_t)buf * FL_BUF;

        float s[16][4];
        #pragma unroll
        for (int j = 0; j < 16; j++)
            #pragma unroll
            for (int q = 0; q < 4; q++) s[j][q] = 0.f;
        #pragma unroll
        for (int ks = 0; ks < 4; ++ks){
            uint32_t bh[8][4];
            #pragma unroll
            for (int nt2 = 0; nt2 < 8; ++nt2){
                uint32_t roff = (uint32_t)((nt2*16 + m_local)*PADQ + ks*16 + k_off)*2;
                ldm_x4(bh[nt2], kb + roff);
            }
            #pragma unroll
            for (int nt = 0; nt < 16; ++nt){
                int q = nt >> 1, rs = nt & 1;
                mma16816(s[nt], qf[ks], bh[q][rs], bh[q][rs+2]);
            }
        }

        bool diag = (c == rb);
        float cm0 = -1e30f, cm1 = -1e30f;
        #pragma unroll
        for (int nt = 0; nt < 16; ++nt){
            int cl = nt*8 + colb;
            int r_lo = wid*16 + rA, r_hi = r_lo + 8;
            #pragma unroll
            for (int q = 0; q < 4; q++) s[nt][q] *= 0.125f;
            if (diag){
                if (cl     > r_lo) s[nt][0] = -1e30f;
                if (cl + 1 > r_lo) s[nt][1] = -1e30f;
                if (cl     > r_hi) s[nt][2] = -1e30f;
                if (cl + 1 > r_hi) s[nt][3] = -1e30f;
            }
            cm0 = fmaxf(cm0, fmaxf(s[nt][0], s[nt][1]));
            cm1 = fmaxf(cm1, fmaxf(s[nt][2], s[nt][3]));
        }
        cm0 = fmaxf(cm0, __shfl_xor_sync(0xffffffffu, cm0, 1));
        cm0 = fmaxf(cm0, __shfl_xor_sync(0xffffffffu, cm0, 2));
        cm1 = fmaxf(cm1, __shfl_xor_sync(0xffffffffu, cm1, 1));
        cm1 = fmaxf(cm1, __shfl_xor_sync(0xffffffffu, cm1, 2));
        float mn0 = fmaxf(m0, cm0), mn1 = fmaxf(m1, cm1);
        float al0 = expf(m0 - mn0), al1 = expf(m1 - mn1);
        m0 = mn0; m1 = mn1;

        float ls0 = 0.f, ls1 = 0.f;
        #pragma unroll
        for (int nt = 0; nt < 16; ++nt){
            s[nt][0] = expf(s[nt][0] - mn0);
            s[nt][1] = expf(s[nt][1] - mn0);
            s[nt][2] = expf(s[nt][2] - mn1);
            s[nt][3] = expf(s[nt][3] - mn1);
            ls0 += s[nt][0] + s[nt][1];
            ls1 += s[nt][2] + s[nt][3];
        }
        ls0 += __shfl_xor_sync(0xffffffffu, ls0, 1);
        ls0 += __shfl_xor_sync(0xffffffffu, ls0, 2);
        ls1 += __shfl_xor_sync(0xffffffffu, ls1, 1);
        ls1 += __shfl_xor_sync(0xffffffffu, ls1, 2);
        l0 = l0 * al0 + ls0;
        l1 = l1 * al1 + ls1;

        #pragma unroll
        for (int nt = 0; nt < 8; ++nt){
            oacc[nt][0] *= al0; oacc[nt][1] *= al0;
            oacc[nt][2] *= al1; oacc[nt][3] *= al1;
        }

        uint32_t vb = kb + FL_KV;
        #pragma unroll
        for (int kk = 0; kk < 8; ++kk){
            uint32_t a[4];
            a[0] = pack_h2(s[2*kk][0],   s[2*kk][1]);
            a[1] = pack_h2(s[2*kk][2],   s[2*kk][3]);
            a[2] = pack_h2(s[2*kk+1][0], s[2*kk+1][1]);
            a[3] = pack_h2(s[2*kk+1][2], s[2*kk+1][3]);
            uint32_t bv[4][4];
            #pragma unroll
            for (int g2 = 0; g2 < 4; ++g2){
                uint32_t voff = (uint32_t)((kk*16 + t_row)*PADQ + g2*16 + t_col)*2;
                ldm_x4_t(bv[g2], vb + voff);
            }
            #pragma unroll
            for (int nt = 0; nt < 8; ++nt){
                int g2 = nt >> 1, sub = (nt & 1) * 2;
                mma16816(oacc[nt], a, bv[g2][sub], bv[g2][sub+1]);
            }
        }
    }

    float inv0 = 1.f / l0, inv1 = 1.f / l1;
    #pragma unroll
    for (int nt = 0; nt < 8; ++nt){
        long row = row0 + wid*16 + rA;
        long col = nt*8 + colb;
        size_t idx = (size_t)(obase + row*(long)DD + col);
        store_half2(oh, idx,        oacc[nt][0]*inv0, oacc[nt][1]*inv0);
        store_half2(oh, idx + 8*DD, oacc[nt][2]*inv1, oacc[nt][3]*inv1);
    }
}

// ================= pointwise ================================================
__global__ __launch_bounds__(256) void add_ln_k(float* __restrict__ h,
                                                const __half* __restrict__ delta,
                                                const float* __restrict__ w,
                                                const float* __restrict__ b,
                                                float* __restrict__ out2){
    long t = blockIdx.x;
    int tid = threadIdx.x;
    int j = tid * 4;
    __shared__ float sh[8];
    float4 hv = *(const float4*)(h + t * DD + j);
    __half2 d0 = *(const __half2*)(delta + t * DD + j);
    __half2 d1 = *(const __half2*)(delta + t * DD + j + 2);
    float x[4] = {hv.x + __low2float(d0), hv.y + __high2float(d0),
                  hv.z + __low2float(d1), hv.w + __high2float(d1)};
    float s = x[0] + x[1] + x[2] + x[3];
    float mean = blockSum256(s, sh) * (1.f / DD);
    float sq = 0.f;
    #pragma unroll
    for (int c = 0; c < 4; c++){ float d = x[c] - mean; sq += d * d; }
    float var = blockSum256(sq, sh) * (1.f / DD);
    float inv = rsqrtf(var + 1e-5f);
    float4 o;
    o.x = (x[0]-mean)*inv*w[j+0] + b[j+0];
    o.y = (x[1]-mean)*inv*w[j+1] + b[j+1];
    o.z = (x[2]-mean)*inv*w[j+2] + b[j+2];
    o.w = (x[3]-mean)*inv*w[j+3] + b[j+3];
    size_t idx = (size_t)t * DD + j;
    *(float4*)(h + idx) = o;
    store_half4(g_hh, idx, o);
    if (out2) *(float4*)(out2 + idx) = o;
}

// ================= launch ===================================================
extern "C" void kernel_launch(void* const* d_in, const int* in_sizes, int n_in,
                              void* d_out, int out_size)
{
    const int*   x    = (const int*)  d_in[0];
    const float* tok  = (const float*)d_in[1];
    const float* pos  = (const float*)d_in[2];
    const float* Wq   = (const float*)d_in[3];
    const float* bq   = (const float*)d_in[4];
    const float* Wk   = (const float*)d_in[5];
    const float* bk   = (const float*)d_in[6];
    const float* Wv   = (const float*)d_in[7];
    const float* bv   = (const float*)d_in[8];
    const float* Wo   = (const float*)d_in[9];
    const float* bo   = (const float*)d_in[10];
    const float* ln1w = (const float*)d_in[11];
    const float* ln1b = (const float*)d_in[12];
    const float* ln2w = (const float*)d_in[13];
    const float* ln2b = (const float*)d_in[14];
    const float* W1   = (const float*)d_in[15];
    const float* b1   = (const float*)d_in[16];
    const float* W2   = (const float*)d_in[17];
    const float* b2   = (const float*)d_in[18];
    const float* Wout = (const float*)d_in[19];
    const float* bout = (const float*)d_in[20];
    float* out = (float*)d_out;

    static int init_done = 0;
    static cudaStream_t s2;
    static cudaEvent_t evF, evJ;
    if (!init_done){
        cudaFuncSetAttribute(gemm_nn, cudaFuncAttributeMaxDynamicSharedMemorySize, GM_SMEM);
        cudaFuncSetAttribute(flash_k, cudaFuncAttributeMaxDynamicSharedMemorySize, FL_SMEM);
        cudaStreamCreateWithFlags(&s2, cudaStreamNonBlocking);
        cudaEventCreateWithFlags(&evF, cudaEventDisableTiming);
        cudaEventCreateWithFlags(&evJ, cudaEventDisableTiming);
        init_done = 1;
    }

    float *h, *bqkv;
    __half *hh, *qh, *oh, *ffh, *th;
    __half *wqn, *won, *w1n, *w2n, *woutn;
    cudaGetSymbolAddress((void**)&h,    g_h);
    cudaGetSymbolAddress((void**)&bqkv, g_bqkv);
    cudaGetSymbolAddress((void**)&hh,   g_hh);
    cudaGetSymbolAddress((void**)&qh,   g_qkvh);
    cudaGetSymbolAddress((void**)&oh,   g_oh);
    cudaGetSymbolAddress((void**)&ffh,  g_ffh);
    cudaGetSymbolAddress((void**)&th,   g_th);
    cudaGetSymbolAddress((void**)&wqn,  g_wqkvn);
    cudaGetSymbolAddress((void**)&won,  g_wo_n);
    cudaGetSymbolAddress((void**)&w1n,  g_w1_n);
    cudaGetSymbolAddress((void**)&w2n,  g_w2_n);
    cudaGetSymbolAddress((void**)&woutn,g_woutn);

    // --- fork: big weight casts on side stream, hidden under QKV+flash ---
    cudaEventRecord(evF, 0);
    cudaStreamWaitEvent(s2, evF, 0);
    cast32_k<<<256,  256, 0, s2>>>(Wo,   won);
    cast32_k<<<1024, 256, 0, s2>>>(W1,   w1n);
    cast32_k<<<1024, 256, 0, s2>>>(W2,   w2n);
    cast32_k<<<4000, 256, 0, s2>>>(Wout, woutn);
    cudaEventRecord(evJ, s2);

    // --- main stream: immediate deps only ---
    packbias_k<<<24, 256>>>(bq, bk, bv);
    qkvpack_k<<<dim3(1024,1,3), 256>>>(Wq, Wk, Wv, wqn);
    embed_k<<<BS, 256>>>(x, tok, pos);

    for (int l = 0; l < LL; l++){
        gemm_nn<<<dim3(BS/128, 3*DD/128), 256, GM_SMEM>>>(
            hh, wqn + (long)l*DD*3*DD, bqkv + (long)l*3*DD,
            0, qh, DD, 3*DD, 3*DD, 2);
        flash_k<<<dim3(HH*BB, SS/128), 256, FL_SMEM>>>(qh, oh);
        if (l == 0) cudaStreamWaitEvent(0, evJ, 0);   // join before first Wo use
        gemm_nn<<<dim3(BS/128, DD/128), 256, GM_SMEM>>>(
            oh, won + (long)l*DD*DD, bo + (long)l*DD,
            0, th, DD, DD, DD, 2);
        add_ln_k<<<BS, 256>>>(h, th, ln1w + (long)l*DD, ln1b + (long)l*DD, 0);
        gemm_nn<<<dim3(BS/128, FFD/128), 256, GM_SMEM>>>(
            hh, w1n + (long)l*DD*FFD, b1 + (long)l*FFD,
            0, ffh, DD, FFD, FFD, 1);
        gemm_nn<<<dim3(BS/128, DD/128), 256, GM_SMEM>>>(
            ffh, w2n + (long)l*FFD*DD, b2 + (long)l*DD,
            0, th, FFD, DD, DD, 2);
        add_ln_k<<<BS, 256>>>(h, th, ln2w + (long)l*DD, ln2b + (long)l*DD,
                              (l == LL-1) ? (out + (long)BS*VV) : 0);
    }

    gemm_nn<<<dim3(BS/128, VV/128), 256, GM_SMEM>>>(
        hh, woutn, bout, out, 0, DD, VV, VV, 0);
}